// round 8
// baseline (speedup 1.0000x reference)
#include <cuda_runtime.h>
#include <cuda_bf16.h>
#include <cuda_fp16.h>
#include <cstdint>

#define NB 16384
#define NV 1024
#define NH 1024
#define NC 64
#define NSTEPS 25
#define NCHAIN (2 * NSTEPS)
#define TILES_PER_STEP 1024          // 128 m-blocks x 8 n-blocks

// ---------------------------------------------------------------------------
// Scratch (static __device__ allocations; no cudaMalloc anywhere)
// ---------------------------------------------------------------------------
__device__ float g_bmod[NB * NV];               // 64 MB
__device__ float g_cmod[NB * NH];               // 64 MB
__device__ __half g_v[NB * NV];                 // 32 MB (current v, 0/1 fp16)
__device__ __half g_h[NB * NH];                 // 32 MB
__device__ __nv_bfloat16 g_v_bf[NB * NV];       // 32 MB (v_model as bf16, FE)
__device__ __nv_bfloat16 g_vd_bf[NB * NV];      // 32 MB (v_data as bf16, FE)
__device__ __half g_Wh[NV * NH];                // W fp16 [V][H]
__device__ __half g_WTh[NH * NV];               // W^T fp16 [H][V]
__device__ __nv_bfloat16 g_WTb1[NH * NV];       // W^T bf16 hi split (FE)
__device__ __nv_bfloat16 g_WTb2[NH * NV];       // W^T bf16 lo split (FE)
__device__ float g_fe_d[NB];
__device__ float g_fe_m[NB];
__device__ float g_fep_d[NB * 16];
__device__ float g_fep_m[NB * 16];
__device__ int g_tick[NCHAIN];                  // per-chain-step tile tickets

// ---------------------------------------------------------------------------
// threefry2x32 (exact JAX semantics, jax_threefry_partitionable)
// ---------------------------------------------------------------------------
__host__ __device__ __forceinline__ void threefry(uint32_t k0, uint32_t k1,
                                                  uint32_t x0, uint32_t x1,
                                                  uint32_t& o0, uint32_t& o1)
{
    uint32_t ks2 = k0 ^ k1 ^ 0x1BD11BDAu;
#define TF_ROT(x, r) (((x) << (r)) | ((x) >> (32 - (r))))
#define TF_RND(r) { x0 += x1; x1 = TF_ROT(x1, r); x1 ^= x0; }
    x0 += k0; x1 += k1;
    TF_RND(13) TF_RND(15) TF_RND(26) TF_RND(6)
    x0 += k1; x1 += ks2 + 1u;
    TF_RND(17) TF_RND(29) TF_RND(16) TF_RND(24)
    x0 += ks2; x1 += k0 + 2u;
    TF_RND(13) TF_RND(15) TF_RND(26) TF_RND(6)
    x0 += k0; x1 += k1 + 3u;
    TF_RND(17) TF_RND(29) TF_RND(16) TF_RND(24)
    x0 += k1; x1 += ks2 + 4u;
    TF_RND(13) TF_RND(15) TF_RND(26) TF_RND(6)
    x0 += ks2; x1 += k0 + 5u;
    o0 = x0; o1 = x1;
#undef TF_RND
#undef TF_ROT
}

__device__ __forceinline__ float urand(uint32_t k0, uint32_t k1, uint32_t idx)
{
    uint32_t a, b;
    threefry(k0, k1, 0u, idx, a, b);
    uint32_t bits = a ^ b;
    return __uint_as_float((bits >> 9) | 0x3F800000u) - 1.0f;
}

// ---------------------------------------------------------------------------
// MMA / ldmatrix / cp.async helpers (baseline PTX, legal on plain sm_103)
// ---------------------------------------------------------------------------
__device__ __forceinline__ uint32_t smem_u32(const void* p) {
    uint32_t a;
    asm("{ .reg .u64 t; cvta.to.shared.u64 t, %1; cvt.u32.u64 %0, t; }" : "=r"(a) : "l"(p));
    return a;
}
__device__ __forceinline__ void ldsm4(uint32_t* r, uint32_t addr) {
    asm volatile("ldmatrix.sync.aligned.m8n8.x4.shared.b16 {%0,%1,%2,%3}, [%4];"
                 : "=r"(r[0]), "=r"(r[1]), "=r"(r[2]), "=r"(r[3]) : "r"(addr));
}
__device__ __forceinline__ void mma_bf16(float* d, const uint32_t* a, uint32_t b0, uint32_t b1) {
    asm volatile("mma.sync.aligned.m16n8k16.row.col.f32.bf16.bf16.f32 "
                 "{%0,%1,%2,%3}, {%4,%5,%6,%7}, {%8,%9}, {%0,%1,%2,%3};"
                 : "+f"(d[0]), "+f"(d[1]), "+f"(d[2]), "+f"(d[3])
                 : "r"(a[0]), "r"(a[1]), "r"(a[2]), "r"(a[3]), "r"(b0), "r"(b1));
}
__device__ __forceinline__ void mma_f16(float* d, const uint32_t* a, uint32_t b0, uint32_t b1) {
    asm volatile("mma.sync.aligned.m16n8k16.row.col.f32.f16.f16.f32 "
                 "{%0,%1,%2,%3}, {%4,%5,%6,%7}, {%8,%9}, {%0,%1,%2,%3};"
                 : "+f"(d[0]), "+f"(d[1]), "+f"(d[2]), "+f"(d[3])
                 : "r"(a[0]), "r"(a[1]), "r"(a[2]), "r"(a[3]), "r"(b0), "r"(b1));
}
#define CP_ASYNC16(dst, src) \
    asm volatile("cp.async.cg.shared.global [%0], [%1], 16;" :: "r"(dst), "l"(src))
#define CP_COMMIT() asm volatile("cp.async.commit_group;")
#define CP_WAIT1()  asm volatile("cp.async.wait_group 1;")
#define CP_WAIT0()  asm volatile("cp.async.wait_group 0;")
#define NAMED_BAR(id, cnt) asm volatile("bar.sync %0, %1;" :: "r"(id), "r"(cnt) : "memory")

__device__ __forceinline__ uint32_t swz(uint32_t off) {  // SW128 on 128B rows
    return off ^ ((off >> 3) & 0x70);
}

// ---------------------------------------------------------------------------
// W -> fp16 plane (both orientations) + bf16 2-way split of W^T (for FE)
// ---------------------------------------------------------------------------
__global__ void split_kernel(const float* __restrict__ W)
{
    __shared__ __half tf[32][33];
    __shared__ __nv_bfloat16 t1[32][33], t2[32][33];
    int bx = blockIdx.x * 32;   // h
    int by = blockIdx.y * 32;   // v
    int tx = threadIdx.x, ty = threadIdx.y;  // 32 x 8
    #pragma unroll
    for (int i = 0; i < 32; i += 8) {
        float w = W[(size_t)(by + ty + i) * NH + bx + tx];
        __half hf = __float2half(w);
        __nv_bfloat16 h1 = __float2bfloat16(w);
        float r = w - __bfloat162float(h1);
        __nv_bfloat16 h2 = __float2bfloat16(r);
        size_t o = (size_t)(by + ty + i) * NH + bx + tx;
        g_Wh[o] = hf;
        tf[ty + i][tx] = hf; t1[ty + i][tx] = h1; t2[ty + i][tx] = h2;
    }
    __syncthreads();
    #pragma unroll
    for (int i = 0; i < 32; i += 8) {
        size_t o = (size_t)(bx + ty + i) * NV + by + tx;
        g_WTh[o]  = tf[tx][ty + i];
        g_WTb1[o] = t1[tx][ty + i];
        g_WTb2[o] = t2[tx][ty + i];
    }
}

// ---------------------------------------------------------------------------
// Conditioning MLP -> b_mod, c_mod  (16 rows per block)
// ---------------------------------------------------------------------------
#define PROWS 16
__global__ void params_kernel(const float* __restrict__ cond, const float* __restrict__ b,
                              const float* __restrict__ c, const float* __restrict__ W1,
                              const float* __restrict__ b1, const float* __restrict__ W2,
                              const float* __restrict__ b2)
{
    __shared__ float sc[PROWS][NC];
    __shared__ float st[PROWS][NC];
    int row0 = blockIdx.x * PROWS;
    int tid = threadIdx.x;  // 256

    for (int i = tid; i < PROWS * NC; i += 256)
        sc[i / NC][i % NC] = cond[(size_t)(row0 + i / NC) * NC + (i % NC)];
    __syncthreads();
    for (int i = tid; i < PROWS * NC; i += 256) {
        int r = i / NC, j = i % NC;
        float s = b1[j];
        #pragma unroll 8
        for (int k = 0; k < NC; k++) s += sc[r][k] * W1[k * NC + j];
        st[r][j] = tanhf(s);
    }
    __syncthreads();

    for (int q = tid; q < NV; q += 256) {
        float ga[PROWS], be[PROWS];
        float ig = b2[q], ib = b2[NV + q];
        #pragma unroll
        for (int r = 0; r < PROWS; r++) { ga[r] = ig; be[r] = ib; }
        for (int k = 0; k < NC; k++) {
            float wg = W2[(size_t)k * 4096 + q];
            float wb = W2[(size_t)k * 4096 + NV + q];
            #pragma unroll
            for (int r = 0; r < PROWS; r++) { ga[r] += st[r][k] * wg; be[r] += st[r][k] * wb; }
        }
        float bq = b[q];
        #pragma unroll
        for (int r = 0; r < PROWS; r++)
            g_bmod[(size_t)(row0 + r) * NV + q] = (1.0f + ga[r]) * bq + be[r];
    }
    for (int q = tid; q < NH; q += 256) {
        float ga[PROWS], be[PROWS];
        float ig = b2[2 * NV + q], ib = b2[2 * NV + NH + q];
        #pragma unroll
        for (int r = 0; r < PROWS; r++) { ga[r] = ig; be[r] = ib; }
        for (int k = 0; k < NC; k++) {
            float wg = W2[(size_t)k * 4096 + 2 * NV + q];
            float wb = W2[(size_t)k * 4096 + 2 * NV + NH + q];
            #pragma unroll
            for (int r = 0; r < PROWS; r++) { ga[r] += st[r][k] * wg; be[r] += st[r][k] * wb; }
        }
        float cq = c[q];
        #pragma unroll
        for (int r = 0; r < PROWS; r++)
            g_cmod[(size_t)(row0 + r) * NH + q] = (1.0f + ga[r]) * cq + be[r];
    }
}

// ---------------------------------------------------------------------------
// init / conversion / reset kernels
// ---------------------------------------------------------------------------
__global__ void init_v_kernel(uint32_t k0, uint32_t k1)
{
    uint32_t i = blockIdx.x * blockDim.x + threadIdx.x;
    float u = urand(k0, k1, i);
    ((uint16_t*)g_v)[i] = (u < 0.5f) ? 0x3C00u : 0u;   // fp16 1.0 / 0.0
}
__global__ void conv_vdata_kernel(const float* __restrict__ vd)
{
    uint32_t i = blockIdx.x * blockDim.x + threadIdx.x;
    g_vd_bf[i] = __float2bfloat16(vd[i]);
}
__global__ void conv_vmodel_kernel()
{
    uint32_t i = blockIdx.x * blockDim.x + threadIdx.x;
    g_v_bf[i] = (((const uint16_t*)g_v)[i] == 0x3C00u) ? __float2bfloat16(1.0f)
                                                       : __float2bfloat16(0.0f);
}
__global__ void reset_kernel()
{
    int i = threadIdx.x;
    if (i < NCHAIN) g_tick[i] = 0;
}

// ---------------------------------------------------------------------------
// Warp-specialized chain GEMM step.
// 512 threads: warps 0-7 = producers (cp.async + ldmatrix + HMMA + z-spill),
// warps 8-15 = consumers (bias + sigmoid + threefry + store).
// Smem: stage0[32K] stage1[32K] | z[128*132*4 = 67584]  -> 133120 B total.
// Named barriers: 0 = "z ready", 1 = "z free", 2 = producer-internal sync.
// ---------------------------------------------------------------------------
#define CH_STAGE 32768
#define CH_ZOFF  65536
#define CH_SMEM  (CH_ZOFF + 128 * 132 * 4)   // 133120

__device__ __forceinline__ void ch_stage_load(uint32_t s_stage,
    const uint16_t* A, const uint16_t* B, int m0, int n0, int kk, int ptid)
{
    #pragma unroll
    for (int r = 0; r < 8; r++) {
        int i = ptid + r * 256;         // 0..2047
        int buf = i >> 10;              // 0:A 1:B
        int row = (i >> 3) & 127;
        int ch  = i & 7;
        const char* src = buf == 0
            ? (const char*)A + (size_t)(m0 + row) * 2048 + kk * 128 + ch * 16
            : (const char*)B + (size_t)(n0 + row) * 2048 + kk * 128 + ch * 16;
        uint32_t off = (uint32_t)(row * 128 + ch * 16);
        CP_ASYNC16(s_stage + buf * 16384 + swz(off), src);
    }
    CP_COMMIT();
}

__global__ void __launch_bounds__(512, 1)
chain_step_kernel(const uint16_t* __restrict__ A, const uint16_t* __restrict__ B,
                  const float* __restrict__ bias, uint16_t* __restrict__ Out,
                  int* __restrict__ tick, uint32_t k0, uint32_t k1)
{
    extern __shared__ char smem[];
    __shared__ int s_tile[2];
    const uint32_t sbase = smem_u32(smem);
    float* zs = (float*)(smem + CH_ZOFF);
    const int tid = threadIdx.x;
    int par = 0;

    if (tid < 256) {
        // ---------------- producers ----------------
        const int wid = tid >> 5, lane = tid & 31;
        const int warp_m = wid & 1, warp_n = wid >> 1;
        const int la = lane & 15, ha = lane >> 4;
        for (;;) {
            if (tid == 0) s_tile[par] = atomicAdd(tick, 1);
            NAMED_BAR(2, 256);
            const int t = s_tile[par];
            float acc[4][4][4];
            if (t < TILES_PER_STEP) {
                const int m0 = (t >> 3) * 128, n0 = (t & 7) * 128;
                #pragma unroll
                for (int i = 0; i < 4; i++)
                    #pragma unroll
                    for (int j = 0; j < 4; j++)
                        #pragma unroll
                        for (int q = 0; q < 4; q++) acc[i][j][q] = 0.0f;
                ch_stage_load(sbase, A, B, m0, n0, 0, tid);
                #pragma unroll 1
                for (int kk = 0; kk < 16; kk++) {
                    const uint32_t s = sbase + (uint32_t)(kk & 1) * CH_STAGE;
                    if (kk + 1 < 16) {
                        ch_stage_load(sbase + (uint32_t)((kk + 1) & 1) * CH_STAGE, A, B, m0, n0, kk + 1, tid);
                        CP_WAIT1();
                    } else {
                        CP_WAIT0();
                    }
                    NAMED_BAR(2, 256);
                    #pragma unroll
                    for (int ks = 0; ks < 4; ks++) {
                        uint32_t a[4][4];
                        #pragma unroll
                        for (int mt = 0; mt < 4; mt++) {
                            uint32_t off = (uint32_t)((warp_m * 64 + mt * 16 + la) * 128 + ks * 32 + ha * 16);
                            ldsm4(a[mt], s + swz(off));
                        }
                        uint32_t b[2][4];
                        #pragma unroll
                        for (int g = 0; g < 2; g++) {
                            uint32_t off = (uint32_t)((warp_n * 32 + g * 16 + la) * 128 + ks * 32 + ha * 16);
                            ldsm4(b[g], s + 16384u + swz(off));
                        }
                        #pragma unroll
                        for (int mt = 0; mt < 4; mt++)
                            #pragma unroll
                            for (int n8 = 0; n8 < 4; n8++)
                                mma_f16(acc[mt][n8], a[mt], b[n8 >> 1][n8 & 1], b[n8 >> 1][(n8 & 1) + 2]);
                    }
                    NAMED_BAR(2, 256);
                }
            }
            NAMED_BAR(1, 512);               // wait: consumers done with previous z
            if (t < TILES_PER_STEP) {
                #pragma unroll
                for (int mt = 0; mt < 4; mt++)
                    #pragma unroll
                    for (int n8 = 0; n8 < 4; n8++) {
                        int r = warp_m * 64 + mt * 16 + (lane >> 2);
                        int cc = warp_n * 32 + n8 * 8 + (lane & 3) * 2;
                        zs[r * 132 + cc]           = acc[mt][n8][0];
                        zs[r * 132 + cc + 1]       = acc[mt][n8][1];
                        zs[(r + 8) * 132 + cc]     = acc[mt][n8][2];
                        zs[(r + 8) * 132 + cc + 1] = acc[mt][n8][3];
                    }
            }
            NAMED_BAR(0, 512);               // signal: z ready (or sentinel)
            if (t >= TILES_PER_STEP) return;
            par ^= 1;
        }
    } else {
        // ---------------- consumers ----------------
        const int ctid = tid - 256;
        for (;;) {
            NAMED_BAR(1, 512);               // signal: z free
            NAMED_BAR(0, 512);               // wait: z ready
            const int t = s_tile[par];
            if (t >= TILES_PER_STEP) return;
            const int m0 = (t >> 3) * 128, n0 = (t & 7) * 128;
            const int rloc = ctid >> 1;
            const int c0 = (ctid & 1) * 64;
            const int row = m0 + rloc;
            const float* zrow = zs + rloc * 132 + c0;
            const float4* bp = (const float4*)(bias + (size_t)row * 1024 + n0 + c0);
            const uint32_t ibase = (uint32_t)(row * 1024 + n0 + c0);
            uint4* op = (uint4*)(Out + (size_t)row * 1024 + n0 + c0);
            #pragma unroll 1
            for (int j0 = 0; j0 < 64; j0 += 8) {
                float4 bv0 = bp[j0 / 4], bv1 = bp[j0 / 4 + 1];
                float zb[8] = {bv0.x, bv0.y, bv0.z, bv0.w, bv1.x, bv1.y, bv1.z, bv1.w};
                uint32_t pk[4];
                #pragma unroll
                for (int jj = 0; jj < 8; jj += 2) {
                    float z0 = zrow[j0 + jj] + zb[jj];
                    float z1 = zrow[j0 + jj + 1] + zb[jj + 1];
                    float e0 = __expf(-z0), e1 = __expf(-z1);
                    float u0 = urand(k0, k1, ibase + (uint32_t)(j0 + jj));
                    float u1 = urand(k0, k1, ibase + (uint32_t)(j0 + jj) + 1u);
                    uint32_t s0 = (fmaf(u0, e0, u0) < 1.0f) ? 0x3C00u : 0u;  // fp16 1.0
                    uint32_t s1 = (fmaf(u1, e1, u1) < 1.0f) ? 0x3C00u : 0u;
                    pk[jj >> 1] = s0 | (s1 << 16);
                }
                op[j0 / 8] = make_uint4(pk[0], pk[1], pk[2], pk[3]);
            }
            par ^= 1;
        }
    }
}

// ---------------------------------------------------------------------------
// FE GEMM (bf16 2-split, softplus partials) — classic 256-thread tiles
// ---------------------------------------------------------------------------
#define FE_STAGE 49152
#define FE_SMEM  (2 * FE_STAGE)

__device__ __forceinline__ void fe_stage_load(uint32_t s_stage,
    const uint16_t* A, const uint16_t* B1, const uint16_t* B2,
    int m0, int n0, int kk, int tid)
{
    #pragma unroll
    for (int r = 0; r < 12; r++) {
        int i = tid + r * 256;
        int buf = i >> 10;              // 0:A 1:B1 2:B2
        int row = (i >> 3) & 127;
        int ch  = i & 7;
        const char* src;
        if (buf == 0)      src = (const char*)A  + (size_t)(m0 + row) * 2048 + kk * 128 + ch * 16;
        else if (buf == 1) src = (const char*)B1 + (size_t)(n0 + row) * 2048 + kk * 128 + ch * 16;
        else               src = (const char*)B2 + (size_t)(n0 + row) * 2048 + kk * 128 + ch * 16;
        uint32_t off = (uint32_t)(row * 128 + ch * 16);
        CP_ASYNC16(s_stage + buf * 16384 + swz(off), src);
    }
    CP_COMMIT();
}

__global__ void __launch_bounds__(256, 2)
fe_kernel(const uint16_t* __restrict__ A,
          const uint16_t* __restrict__ B1,
          const uint16_t* __restrict__ B2,
          const float* __restrict__ bias,
          float* __restrict__ fe_part)
{
    extern __shared__ char smem[];
    const uint32_t sbase = smem_u32(smem);
    const int tid = threadIdx.x;
    const int wid = tid >> 5, lane = tid & 31;
    const int warp_m = wid & 1, warp_n = wid >> 1;
    const int la = lane & 15, ha = lane >> 4;
    const int m0 = blockIdx.y * 128;
    const int n0 = blockIdx.x * 128;

    float acc[4][4][4];
    #pragma unroll
    for (int i = 0; i < 4; i++)
        #pragma unroll
        for (int j = 0; j < 4; j++)
            #pragma unroll
            for (int q = 0; q < 4; q++) acc[i][j][q] = 0.0f;

    fe_stage_load(sbase, A, B1, B2, m0, n0, 0, tid);

    #pragma unroll 1
    for (int kk = 0; kk < 16; kk++) {
        const uint32_t s = sbase + (uint32_t)(kk & 1) * FE_STAGE;
        if (kk + 1 < 16) {
            fe_stage_load(sbase + (uint32_t)((kk + 1) & 1) * FE_STAGE, A, B1, B2, m0, n0, kk + 1, tid);
            CP_WAIT1();
        } else {
            CP_WAIT0();
        }
        __syncthreads();
        #pragma unroll
        for (int ks = 0; ks < 4; ks++) {
            uint32_t a[4][4];
            #pragma unroll
            for (int mt = 0; mt < 4; mt++) {
                uint32_t off = (uint32_t)((warp_m * 64 + mt * 16 + la) * 128 + ks * 32 + ha * 16);
                ldsm4(a[mt], s + swz(off));
            }
            #pragma unroll
            for (int sp = 0; sp < 2; sp++) {
                uint32_t b[2][4];
                #pragma unroll
                for (int g = 0; g < 2; g++) {
                    uint32_t off = (uint32_t)((warp_n * 32 + g * 16 + la) * 128 + ks * 32 + ha * 16);
                    ldsm4(b[g], s + 16384u * (1 + sp) + swz(off));
                }
                #pragma unroll
                for (int mt = 0; mt < 4; mt++)
                    #pragma unroll
                    for (int n8 = 0; n8 < 4; n8++)
                        mma_bf16(acc[mt][n8], a[mt], b[n8 >> 1][n8 & 1], b[n8 >> 1][(n8 & 1) + 2]);
            }
        }
        __syncthreads();
    }

    float* zs = (float*)smem;
    #pragma unroll
    for (int mt = 0; mt < 4; mt++)
        #pragma unroll
        for (int n8 = 0; n8 < 4; n8++) {
            int r = warp_m * 64 + mt * 16 + (lane >> 2);
            int cc = warp_n * 32 + n8 * 8 + (lane & 3) * 2;
            zs[r * 132 + cc]           = acc[mt][n8][0];
            zs[r * 132 + cc + 1]       = acc[mt][n8][1];
            zs[(r + 8) * 132 + cc]     = acc[mt][n8][2];
            zs[(r + 8) * 132 + cc + 1] = acc[mt][n8][3];
        }
    __syncthreads();

    const int rloc = tid >> 1;
    const int c0 = (tid & 1) * 64;
    const int row = m0 + rloc;
    const float* zrow = zs + rloc * 132 + c0;
    const float4* bp = (const float4*)(bias + (size_t)row * 1024 + n0 + c0);

    float sp_acc = 0.0f;
    #pragma unroll 1
    for (int j0 = 0; j0 < 64; j0 += 8) {
        float4 bv0 = bp[j0 / 4], bv1 = bp[j0 / 4 + 1];
        float zb[8] = {bv0.x, bv0.y, bv0.z, bv0.w, bv1.x, bv1.y, bv1.z, bv1.w};
        #pragma unroll
        for (int jj = 0; jj < 8; jj++) {
            float z = zrow[j0 + jj] + zb[jj];
            sp_acc += fmaxf(z, 0.0f) + log1pf(expf(-fabsf(z)));
        }
    }
    fe_part[(size_t)row * 16 + blockIdx.x * 2 + (tid & 1)] = sp_acc;
}

// ---------------------------------------------------------------------------
// fe[row] = -(v . bmod_row) - sum(fe_part[row, :16])
// ---------------------------------------------------------------------------
__global__ void rowdot_kernel(const __nv_bfloat16* __restrict__ v, const float* __restrict__ bmod,
                              const float* __restrict__ part, float* __restrict__ fe)
{
    int row = blockIdx.x;
    int tid = threadIdx.x;  // 256
    float s = 0.0f;
    for (int q = tid; q < NV; q += 256)
        s += __bfloat162float(v[(size_t)row * NV + q]) * bmod[(size_t)row * NV + q];
    __shared__ float red[8];
    #pragma unroll
    for (int off = 16; off; off >>= 1) s += __shfl_down_sync(0xffffffffu, s, off);
    if ((tid & 31) == 0) red[tid >> 5] = s;
    __syncthreads();
    if (tid == 0) {
        float dsum = 0.0f;
        #pragma unroll
        for (int w = 0; w < 8; w++) dsum += red[w];
        float sp = 0.0f;
        #pragma unroll
        for (int j = 0; j < 16; j++) sp += part[(size_t)row * 16 + j];
        fe[row] = -dsum - sp;
    }
}

__global__ void final_kernel(float* __restrict__ out)
{
    int tid = threadIdx.x;  // 256
    double s = 0.0;
    for (int i = tid; i < NB; i += 256)
        s += (double)g_fe_d[i] - (double)g_fe_m[i];
    __shared__ double red[8];
    #pragma unroll
    for (int off = 16; off; off >>= 1) s += __shfl_down_sync(0xffffffffu, s, off);
    if ((tid & 31) == 0) red[tid >> 5] = s;
    __syncthreads();
    if (tid == 0) {
        double t = 0.0;
        #pragma unroll
        for (int w = 0; w < 8; w++) t += red[w];
        out[0] = (float)(t / (double)NB);
    }
}

// ---------------------------------------------------------------------------
// Host orchestration
// ---------------------------------------------------------------------------
static void host_split_keys(uint32_t& sk0, uint32_t& sk1,
                            uint32_t* ck0, uint32_t* ck1)
{
    uint32_t rk0 = 0u, rk1 = 42u;
    uint32_t c0, c1;
    threefry(rk0, rk1, 0u, 0u, c0, c1);    // k_chain
    threefry(rk0, rk1, 0u, 1u, sk0, sk1);  // k_start
    uint32_t k0 = c0, k1 = c1;
    for (int s = 0; s < NSTEPS; s++) {
        uint32_t nk0, nk1, h0, h1, v0, v1;
        threefry(k0, k1, 0u, 0u, nk0, nk1);
        threefry(k0, k1, 0u, 1u, h0, h1);  // kh
        threefry(k0, k1, 0u, 2u, v0, v1);  // kv
        ck0[2 * s] = h0;     ck1[2 * s] = h1;
        ck0[2 * s + 1] = v0; ck1[2 * s + 1] = v1;
        k0 = nk0; k1 = nk1;
    }
}

extern "C" void kernel_launch(void* const* d_in, const int* in_sizes, int n_in,
                              void* d_out, int out_size)
{
    const float* v_data = (const float*)d_in[0];
    const float* cond   = (const float*)d_in[1];
    const float* W      = (const float*)d_in[2];
    const float* b      = (const float*)d_in[3];
    const float* c      = (const float*)d_in[4];
    const float* W1     = (const float*)d_in[5];
    const float* b1     = (const float*)d_in[6];
    const float* W2     = (const float*)d_in[7];
    const float* b2     = (const float*)d_in[8];
    float* out = (float*)d_out;

    uint32_t sk0, sk1;
    uint32_t ck0[NCHAIN], ck1[NCHAIN];
    host_split_keys(sk0, sk1, ck0, ck1);

    static int n_sm = 0;
    if (n_sm == 0) {
        int dev = 0;
        cudaGetDevice(&dev);
        cudaDeviceGetAttribute(&n_sm, cudaDevAttrMultiProcessorCount, dev);
        if (n_sm <= 0) n_sm = 148;
    }

    cudaFuncSetAttribute(chain_step_kernel, cudaFuncAttributeMaxDynamicSharedMemorySize, CH_SMEM);
    cudaFuncSetAttribute(fe_kernel, cudaFuncAttributeMaxDynamicSharedMemorySize, FE_SMEM);

    uint16_t *p_v, *p_h, *p_Wh, *p_WTh, *p_WTb1, *p_WTb2, *p_vbf, *p_vdbf;
    float *p_bmod, *p_cmod, *p_fed, *p_fem, *p_fpd, *p_fpm;
    int* p_tick;
    cudaGetSymbolAddress((void**)&p_v, g_v);
    cudaGetSymbolAddress((void**)&p_h, g_h);
    cudaGetSymbolAddress((void**)&p_vbf, g_v_bf);
    cudaGetSymbolAddress((void**)&p_vdbf, g_vd_bf);
    cudaGetSymbolAddress((void**)&p_Wh, g_Wh);
    cudaGetSymbolAddress((void**)&p_WTh, g_WTh);
    cudaGetSymbolAddress((void**)&p_WTb1, g_WTb1);
    cudaGetSymbolAddress((void**)&p_WTb2, g_WTb2);
    cudaGetSymbolAddress((void**)&p_bmod, g_bmod);
    cudaGetSymbolAddress((void**)&p_cmod, g_cmod);
    cudaGetSymbolAddress((void**)&p_fed, g_fe_d);
    cudaGetSymbolAddress((void**)&p_fem, g_fe_m);
    cudaGetSymbolAddress((void**)&p_fpd, g_fep_d);
    cudaGetSymbolAddress((void**)&p_fpm, g_fep_m);
    cudaGetSymbolAddress((void**)&p_tick, g_tick);

    // Setup
    reset_kernel<<<1, NCHAIN>>>();
    split_kernel<<<dim3(32, 32), dim3(32, 8)>>>(W);
    params_kernel<<<NB / PROWS, 256>>>(cond, b, c, W1, b1, W2, b2);
    init_v_kernel<<<(NB * NV) / 256, 256>>>(sk0, sk1);
    conv_vdata_kernel<<<(NB * NV) / 256, 256>>>(v_data);

    // Gibbs chain: 50 warp-specialized GEMM steps
    for (int s = 0; s < NCHAIN; s++) {
        const int even = !(s & 1);
        chain_step_kernel<<<n_sm, 512, CH_SMEM>>>(
            even ? p_v : p_h,
            even ? p_WTh : p_Wh,
            even ? p_cmod : p_bmod,
            even ? p_h : p_v,
            p_tick + s, ck0[s], ck1[s]);
    }

    // Free energy
    conv_vmodel_kernel<<<(NB * NV) / 256, 256>>>();
    dim3 ggrid(8, 128);
    fe_kernel<<<ggrid, 256, FE_SMEM>>>(p_vdbf, p_WTb1, p_WTb2, p_cmod, p_fpd);
    fe_kernel<<<ggrid, 256, FE_SMEM>>>(p_vbf, p_WTb1, p_WTb2, p_cmod, p_fpm);
    rowdot_kernel<<<NB, 256>>>((const __nv_bfloat16*)p_vdbf, p_bmod, p_fpd, p_fed);
    rowdot_kernel<<<NB, 256>>>((const __nv_bfloat16*)p_vbf, p_bmod, p_fpm, p_fem);
    final_kernel<<<1, 256>>>(out);
}

// round 9
// speedup vs baseline: 1.2691x; 1.2691x over previous
#include <cuda_runtime.h>
#include <cuda_bf16.h>
#include <cuda_fp16.h>
#include <cstdint>

#define NB 16384
#define NV 1024
#define NH 1024
#define NC 64
#define NSTEPS 25
#define NCHAIN (2 * NSTEPS)

// ---------------------------------------------------------------------------
// Scratch (static __device__ allocations; no cudaMalloc anywhere)
// ---------------------------------------------------------------------------
__device__ float g_bmod[NB * NV];               // 64 MB
__device__ float g_cmod[NB * NH];               // 64 MB
__device__ __half g_v[NB * NV];                 // 32 MB (current v, 0/1 fp16)
__device__ __half g_h[NB * NH];                 // 32 MB
__device__ __nv_bfloat16 g_v_bf[NB * NV];       // 32 MB (v_model as bf16, FE)
__device__ __nv_bfloat16 g_vd_bf[NB * NV];      // 32 MB (v_data as bf16, FE)
__device__ __half g_Wh[NV * NH];                // W fp16 [V][H]
__device__ __half g_WTh[NH * NV];               // W^T fp16 [H][V]
__device__ __nv_bfloat16 g_WTb1[NH * NV];       // W^T bf16 hi split (FE)
__device__ __nv_bfloat16 g_WTb2[NH * NV];       // W^T bf16 lo split (FE)
__device__ float g_fe_d[NB];
__device__ float g_fe_m[NB];
__device__ float g_fep_d[NB * 16];
__device__ float g_fep_m[NB * 16];

// ---------------------------------------------------------------------------
// threefry2x32 (exact JAX semantics, jax_threefry_partitionable)
// ---------------------------------------------------------------------------
__host__ __device__ __forceinline__ void threefry(uint32_t k0, uint32_t k1,
                                                  uint32_t x0, uint32_t x1,
                                                  uint32_t& o0, uint32_t& o1)
{
    uint32_t ks2 = k0 ^ k1 ^ 0x1BD11BDAu;
#define TF_ROT(x, r) (((x) << (r)) | ((x) >> (32 - (r))))
#define TF_RND(r) { x0 += x1; x1 = TF_ROT(x1, r); x1 ^= x0; }
    x0 += k0; x1 += k1;
    TF_RND(13) TF_RND(15) TF_RND(26) TF_RND(6)
    x0 += k1; x1 += ks2 + 1u;
    TF_RND(17) TF_RND(29) TF_RND(16) TF_RND(24)
    x0 += ks2; x1 += k0 + 2u;
    TF_RND(13) TF_RND(15) TF_RND(26) TF_RND(6)
    x0 += k0; x1 += k1 + 3u;
    TF_RND(17) TF_RND(29) TF_RND(16) TF_RND(24)
    x0 += k1; x1 += ks2 + 4u;
    TF_RND(13) TF_RND(15) TF_RND(26) TF_RND(6)
    x0 += ks2; x1 += k0 + 5u;
    o0 = x0; o1 = x1;
#undef TF_RND
#undef TF_ROT
}

__device__ __forceinline__ float urand(uint32_t k0, uint32_t k1, uint32_t idx)
{
    uint32_t a, b;
    threefry(k0, k1, 0u, idx, a, b);
    uint32_t bits = a ^ b;
    return __uint_as_float((bits >> 9) | 0x3F800000u) - 1.0f;
}

// ---------------------------------------------------------------------------
// MMA / ldmatrix / cp.async helpers (baseline PTX, legal on plain sm_103)
// ---------------------------------------------------------------------------
__device__ __forceinline__ uint32_t smem_u32(const void* p) {
    uint32_t a;
    asm("{ .reg .u64 t; cvta.to.shared.u64 t, %1; cvt.u32.u64 %0, t; }" : "=r"(a) : "l"(p));
    return a;
}
__device__ __forceinline__ void ldsm4(uint32_t* r, uint32_t addr) {
    asm volatile("ldmatrix.sync.aligned.m8n8.x4.shared.b16 {%0,%1,%2,%3}, [%4];"
                 : "=r"(r[0]), "=r"(r[1]), "=r"(r[2]), "=r"(r[3]) : "r"(addr));
}
__device__ __forceinline__ void mma_bf16(float* d, const uint32_t* a, uint32_t b0, uint32_t b1) {
    asm volatile("mma.sync.aligned.m16n8k16.row.col.f32.bf16.bf16.f32 "
                 "{%0,%1,%2,%3}, {%4,%5,%6,%7}, {%8,%9}, {%0,%1,%2,%3};"
                 : "+f"(d[0]), "+f"(d[1]), "+f"(d[2]), "+f"(d[3])
                 : "r"(a[0]), "r"(a[1]), "r"(a[2]), "r"(a[3]), "r"(b0), "r"(b1));
}
__device__ __forceinline__ void mma_f16(float* d, const uint32_t* a, uint32_t b0, uint32_t b1) {
    asm volatile("mma.sync.aligned.m16n8k16.row.col.f32.f16.f16.f32 "
                 "{%0,%1,%2,%3}, {%4,%5,%6,%7}, {%8,%9}, {%0,%1,%2,%3};"
                 : "+f"(d[0]), "+f"(d[1]), "+f"(d[2]), "+f"(d[3])
                 : "r"(a[0]), "r"(a[1]), "r"(a[2]), "r"(a[3]), "r"(b0), "r"(b1));
}
#define CP_ASYNC16(dst, src) \
    asm volatile("cp.async.cg.shared.global [%0], [%1], 16;" :: "r"(dst), "l"(src))
#define CP_COMMIT() asm volatile("cp.async.commit_group;")
#define CP_WAIT1()  asm volatile("cp.async.wait_group 1;")
#define CP_WAIT0()  asm volatile("cp.async.wait_group 0;")

__device__ __forceinline__ uint32_t swz(uint32_t off) {  // SW128 on 128B rows
    return off ^ ((off >> 3) & 0x70);
}

// ---------------------------------------------------------------------------
// W -> fp16 plane (both orientations) + bf16 2-way split of W^T (for FE)
// ---------------------------------------------------------------------------
__global__ void split_kernel(const float* __restrict__ W)
{
    __shared__ __half tf[32][33];
    __shared__ __nv_bfloat16 t1[32][33], t2[32][33];
    int bx = blockIdx.x * 32;   // h
    int by = blockIdx.y * 32;   // v
    int tx = threadIdx.x, ty = threadIdx.y;  // 32 x 8
    #pragma unroll
    for (int i = 0; i < 32; i += 8) {
        float w = W[(size_t)(by + ty + i) * NH + bx + tx];
        __half hf = __float2half(w);
        __nv_bfloat16 h1 = __float2bfloat16(w);
        float r = w - __bfloat162float(h1);
        __nv_bfloat16 h2 = __float2bfloat16(r);
        size_t o = (size_t)(by + ty + i) * NH + bx + tx;
        g_Wh[o] = hf;
        tf[ty + i][tx] = hf; t1[ty + i][tx] = h1; t2[ty + i][tx] = h2;
    }
    __syncthreads();
    #pragma unroll
    for (int i = 0; i < 32; i += 8) {
        size_t o = (size_t)(bx + ty + i) * NV + by + tx;
        g_WTh[o]  = tf[tx][ty + i];
        g_WTb1[o] = t1[tx][ty + i];
        g_WTb2[o] = t2[tx][ty + i];
    }
}

// ---------------------------------------------------------------------------
// Conditioning MLP -> b_mod, c_mod  (16 rows per block)
// ---------------------------------------------------------------------------
#define PROWS 16
__global__ void params_kernel(const float* __restrict__ cond, const float* __restrict__ b,
                              const float* __restrict__ c, const float* __restrict__ W1,
                              const float* __restrict__ b1, const float* __restrict__ W2,
                              const float* __restrict__ b2)
{
    __shared__ float sc[PROWS][NC];
    __shared__ float st[PROWS][NC];
    int row0 = blockIdx.x * PROWS;
    int tid = threadIdx.x;  // 256

    for (int i = tid; i < PROWS * NC; i += 256)
        sc[i / NC][i % NC] = cond[(size_t)(row0 + i / NC) * NC + (i % NC)];
    __syncthreads();
    for (int i = tid; i < PROWS * NC; i += 256) {
        int r = i / NC, j = i % NC;
        float s = b1[j];
        #pragma unroll 8
        for (int k = 0; k < NC; k++) s += sc[r][k] * W1[k * NC + j];
        st[r][j] = tanhf(s);
    }
    __syncthreads();

    for (int q = tid; q < NV; q += 256) {
        float ga[PROWS], be[PROWS];
        float ig = b2[q], ib = b2[NV + q];
        #pragma unroll
        for (int r = 0; r < PROWS; r++) { ga[r] = ig; be[r] = ib; }
        for (int k = 0; k < NC; k++) {
            float wg = W2[(size_t)k * 4096 + q];
            float wb = W2[(size_t)k * 4096 + NV + q];
            #pragma unroll
            for (int r = 0; r < PROWS; r++) { ga[r] += st[r][k] * wg; be[r] += st[r][k] * wb; }
        }
        float bq = b[q];
        #pragma unroll
        for (int r = 0; r < PROWS; r++)
            g_bmod[(size_t)(row0 + r) * NV + q] = (1.0f + ga[r]) * bq + be[r];
    }
    for (int q = tid; q < NH; q += 256) {
        float ga[PROWS], be[PROWS];
        float ig = b2[2 * NV + q], ib = b2[2 * NV + NH + q];
        #pragma unroll
        for (int r = 0; r < PROWS; r++) { ga[r] = ig; be[r] = ib; }
        for (int k = 0; k < NC; k++) {
            float wg = W2[(size_t)k * 4096 + 2 * NV + q];
            float wb = W2[(size_t)k * 4096 + 2 * NV + NH + q];
            #pragma unroll
            for (int r = 0; r < PROWS; r++) { ga[r] += st[r][k] * wg; be[r] += st[r][k] * wb; }
        }
        float cq = c[q];
        #pragma unroll
        for (int r = 0; r < PROWS; r++)
            g_cmod[(size_t)(row0 + r) * NH + q] = (1.0f + ga[r]) * cq + be[r];
    }
}

// ---------------------------------------------------------------------------
// init / conversion kernels
// ---------------------------------------------------------------------------
__global__ void init_v_kernel(uint32_t k0, uint32_t k1)
{
    uint32_t i = blockIdx.x * blockDim.x + threadIdx.x;
    float u = urand(k0, k1, i);
    ((uint16_t*)g_v)[i] = (u < 0.5f) ? 0x3C00u : 0u;   // fp16 1.0 / 0.0
}
__global__ void conv_vdata_kernel(const float* __restrict__ vd)
{
    uint32_t i = blockIdx.x * blockDim.x + threadIdx.x;
    g_vd_bf[i] = __float2bfloat16(vd[i]);
}
__global__ void conv_vmodel_kernel()
{
    uint32_t i = blockIdx.x * blockDim.x + threadIdx.x;
    g_v_bf[i] = (((const uint16_t*)g_v)[i] == 0x3C00u) ? __float2bfloat16(1.0f)
                                                       : __float2bfloat16(0.0f);
}

// ---------------------------------------------------------------------------
// Chain GEMM (fp16, 1 plane): Z = A @ B^T + bias -> bernoulli(sigmoid) store.
// 2-stage cp.async, K-chunk 64, warps 2(M)x4(N), register-direct epilogue.
// Smem: 2 x 32 KB stages only (no z spill).
// ---------------------------------------------------------------------------
#define CH_STAGE 32768
#define CH_SMEM  (2 * CH_STAGE)

__device__ __forceinline__ void ch_stage_load(uint32_t s_stage,
    const uint16_t* A, const uint16_t* B, int m0, int n0, int kk, int tid)
{
    #pragma unroll
    for (int r = 0; r < 8; r++) {
        int i = tid + r * 256;          // 0..2047
        int buf = i >> 10;              // 0:A 1:B
        int row = (i >> 3) & 127;
        int ch  = i & 7;
        const char* src = buf == 0
            ? (const char*)A + (size_t)(m0 + row) * 2048 + kk * 128 + ch * 16
            : (const char*)B + (size_t)(n0 + row) * 2048 + kk * 128 + ch * 16;
        uint32_t off = (uint32_t)(row * 128 + ch * 16);
        CP_ASYNC16(s_stage + buf * 16384 + swz(off), src);
    }
    CP_COMMIT();
}

__global__ void __launch_bounds__(256, 2)
chain_step_kernel(const uint16_t* __restrict__ A, const uint16_t* __restrict__ B,
                  const float* __restrict__ bias, uint16_t* __restrict__ Out,
                  uint32_t k0, uint32_t k1)
{
    extern __shared__ char smem[];
    const uint32_t sbase = smem_u32(smem);
    const int tid = threadIdx.x;
    const int wid = tid >> 5, lane = tid & 31;
    const int warp_m = wid & 1, warp_n = wid >> 1;
    const int la = lane & 15, ha = lane >> 4;
    const int m0 = blockIdx.y * 128;
    const int n0 = blockIdx.x * 128;

    float acc[4][4][4];                  // [mt(16m)][n8][frag]
    #pragma unroll
    for (int i = 0; i < 4; i++)
        #pragma unroll
        for (int j = 0; j < 4; j++)
            #pragma unroll
            for (int q = 0; q < 4; q++) acc[i][j][q] = 0.0f;

    ch_stage_load(sbase, A, B, m0, n0, 0, tid);

    #pragma unroll 1
    for (int kk = 0; kk < 16; kk++) {
        const uint32_t s = sbase + (uint32_t)(kk & 1) * CH_STAGE;
        if (kk + 1 < 16) {
            ch_stage_load(sbase + (uint32_t)((kk + 1) & 1) * CH_STAGE, A, B, m0, n0, kk + 1, tid);
            CP_WAIT1();
        } else {
            CP_WAIT0();
        }
        __syncthreads();

        #pragma unroll
        for (int ks = 0; ks < 4; ks++) {
            uint32_t a[4][4];
            #pragma unroll
            for (int mt = 0; mt < 4; mt++) {
                uint32_t off = (uint32_t)((warp_m * 64 + mt * 16 + la) * 128 + ks * 32 + ha * 16);
                ldsm4(a[mt], s + swz(off));
            }
            uint32_t b[2][4];
            #pragma unroll
            for (int g = 0; g < 2; g++) {
                uint32_t off = (uint32_t)((warp_n * 32 + g * 16 + la) * 128 + ks * 32 + ha * 16);
                ldsm4(b[g], s + 16384u + swz(off));
            }
            #pragma unroll
            for (int mt = 0; mt < 4; mt++)
                #pragma unroll
                for (int n8 = 0; n8 < 4; n8++)
                    mma_f16(acc[mt][n8], a[mt], b[n8 >> 1][n8 & 1], b[n8 >> 1][(n8 & 1) + 2]);
        }
        __syncthreads();
    }

    // Register-direct epilogue: each thread owns (row, col..col+1) pairs.
    const int r0 = m0 + warp_m * 64 + (lane >> 2);
    const int cb = n0 + warp_n * 32 + (lane & 3) * 2;
    #pragma unroll
    for (int mt = 0; mt < 4; mt++) {
        #pragma unroll
        for (int n8 = 0; n8 < 4; n8++) {
            const int col = cb + n8 * 8;
            #pragma unroll
            for (int hrow = 0; hrow < 2; hrow++) {
                const int row = r0 + mt * 16 + hrow * 8;
                const uint32_t idx = (uint32_t)(row * 1024 + col);
                const float2 bv = *(const float2*)(bias + idx);
                float z0 = acc[mt][n8][hrow * 2 + 0] + bv.x;
                float z1 = acc[mt][n8][hrow * 2 + 1] + bv.y;
                float e0 = __expf(-z0), e1 = __expf(-z1);
                float u0 = urand(k0, k1, idx);
                float u1 = urand(k0, k1, idx + 1u);
                uint32_t s0 = (fmaf(u0, e0, u0) < 1.0f) ? 0x3C00u : 0u;  // fp16 1.0
                uint32_t s1 = (fmaf(u1, e1, u1) < 1.0f) ? 0x3C00u : 0u;
                *(uint32_t*)(Out + idx) = s0 | (s1 << 16);
            }
        }
    }
}

// ---------------------------------------------------------------------------
// FE GEMM (bf16 2-split, softplus partials) — R6 structure with z-spill
// ---------------------------------------------------------------------------
#define FE_STAGE 49152
#define FE_SMEM  (2 * FE_STAGE)

__device__ __forceinline__ void fe_stage_load(uint32_t s_stage,
    const uint16_t* A, const uint16_t* B1, const uint16_t* B2,
    int m0, int n0, int kk, int tid)
{
    #pragma unroll
    for (int r = 0; r < 12; r++) {
        int i = tid + r * 256;
        int buf = i >> 10;              // 0:A 1:B1 2:B2
        int row = (i >> 3) & 127;
        int ch  = i & 7;
        const char* src;
        if (buf == 0)      src = (const char*)A  + (size_t)(m0 + row) * 2048 + kk * 128 + ch * 16;
        else if (buf == 1) src = (const char*)B1 + (size_t)(n0 + row) * 2048 + kk * 128 + ch * 16;
        else               src = (const char*)B2 + (size_t)(n0 + row) * 2048 + kk * 128 + ch * 16;
        uint32_t off = (uint32_t)(row * 128 + ch * 16);
        CP_ASYNC16(s_stage + buf * 16384 + swz(off), src);
    }
    CP_COMMIT();
}

__global__ void __launch_bounds__(256, 2)
fe_kernel(const uint16_t* __restrict__ A,
          const uint16_t* __restrict__ B1,
          const uint16_t* __restrict__ B2,
          const float* __restrict__ bias,
          float* __restrict__ fe_part)
{
    extern __shared__ char smem[];
    const uint32_t sbase = smem_u32(smem);
    const int tid = threadIdx.x;
    const int wid = tid >> 5, lane = tid & 31;
    const int warp_m = wid & 1, warp_n = wid >> 1;
    const int la = lane & 15, ha = lane >> 4;
    const int m0 = blockIdx.y * 128;
    const int n0 = blockIdx.x * 128;

    float acc[4][4][4];
    #pragma unroll
    for (int i = 0; i < 4; i++)
        #pragma unroll
        for (int j = 0; j < 4; j++)
            #pragma unroll
            for (int q = 0; q < 4; q++) acc[i][j][q] = 0.0f;

    fe_stage_load(sbase, A, B1, B2, m0, n0, 0, tid);

    #pragma unroll 1
    for (int kk = 0; kk < 16; kk++) {
        const uint32_t s = sbase + (uint32_t)(kk & 1) * FE_STAGE;
        if (kk + 1 < 16) {
            fe_stage_load(sbase + (uint32_t)((kk + 1) & 1) * FE_STAGE, A, B1, B2, m0, n0, kk + 1, tid);
            CP_WAIT1();
        } else {
            CP_WAIT0();
        }
        __syncthreads();
        #pragma unroll
        for (int ks = 0; ks < 4; ks++) {
            uint32_t a[4][4];
            #pragma unroll
            for (int mt = 0; mt < 4; mt++) {
                uint32_t off = (uint32_t)((warp_m * 64 + mt * 16 + la) * 128 + ks * 32 + ha * 16);
                ldsm4(a[mt], s + swz(off));
            }
            #pragma unroll
            for (int sp = 0; sp < 2; sp++) {
                uint32_t b[2][4];
                #pragma unroll
                for (int g = 0; g < 2; g++) {
                    uint32_t off = (uint32_t)((warp_n * 32 + g * 16 + la) * 128 + ks * 32 + ha * 16);
                    ldsm4(b[g], s + 16384u * (1 + sp) + swz(off));
                }
                #pragma unroll
                for (int mt = 0; mt < 4; mt++)
                    #pragma unroll
                    for (int n8 = 0; n8 < 4; n8++)
                        mma_bf16(acc[mt][n8], a[mt], b[n8 >> 1][n8 & 1], b[n8 >> 1][(n8 & 1) + 2]);
            }
        }
        __syncthreads();
    }

    float* zs = (float*)smem;
    #pragma unroll
    for (int mt = 0; mt < 4; mt++)
        #pragma unroll
        for (int n8 = 0; n8 < 4; n8++) {
            int r = warp_m * 64 + mt * 16 + (lane >> 2);
            int cc = warp_n * 32 + n8 * 8 + (lane & 3) * 2;
            zs[r * 132 + cc]           = acc[mt][n8][0];
            zs[r * 132 + cc + 1]       = acc[mt][n8][1];
            zs[(r + 8) * 132 + cc]     = acc[mt][n8][2];
            zs[(r + 8) * 132 + cc + 1] = acc[mt][n8][3];
        }
    __syncthreads();

    const int rloc = tid >> 1;
    const int c0 = (tid & 1) * 64;
    const int row = m0 + rloc;
    const float* zrow = zs + rloc * 132 + c0;
    const float4* bp = (const float4*)(bias + (size_t)row * 1024 + n0 + c0);

    float sp_acc = 0.0f;
    #pragma unroll 1
    for (int j0 = 0; j0 < 64; j0 += 8) {
        float4 bv0 = bp[j0 / 4], bv1 = bp[j0 / 4 + 1];
        float zb[8] = {bv0.x, bv0.y, bv0.z, bv0.w, bv1.x, bv1.y, bv1.z, bv1.w};
        #pragma unroll
        for (int jj = 0; jj < 8; jj++) {
            float z = zrow[j0 + jj] + zb[jj];
            sp_acc += fmaxf(z, 0.0f) + log1pf(expf(-fabsf(z)));
        }
    }
    fe_part[(size_t)row * 16 + blockIdx.x * 2 + (tid & 1)] = sp_acc;
}

// ---------------------------------------------------------------------------
// fe[row] = -(v . bmod_row) - sum(fe_part[row, :16])
// ---------------------------------------------------------------------------
__global__ void rowdot_kernel(const __nv_bfloat16* __restrict__ v, const float* __restrict__ bmod,
                              const float* __restrict__ part, float* __restrict__ fe)
{
    int row = blockIdx.x;
    int tid = threadIdx.x;  // 256
    float s = 0.0f;
    for (int q = tid; q < NV; q += 256)
        s += __bfloat162float(v[(size_t)row * NV + q]) * bmod[(size_t)row * NV + q];
    __shared__ float red[8];
    #pragma unroll
    for (int off = 16; off; off >>= 1) s += __shfl_down_sync(0xffffffffu, s, off);
    if ((tid & 31) == 0) red[tid >> 5] = s;
    __syncthreads();
    if (tid == 0) {
        float dsum = 0.0f;
        #pragma unroll
        for (int w = 0; w < 8; w++) dsum += red[w];
        float sp = 0.0f;
        #pragma unroll
        for (int j = 0; j < 16; j++) sp += part[(size_t)row * 16 + j];
        fe[row] = -dsum - sp;
    }
}

__global__ void final_kernel(float* __restrict__ out)
{
    int tid = threadIdx.x;  // 256
    double s = 0.0;
    for (int i = tid; i < NB; i += 256)
        s += (double)g_fe_d[i] - (double)g_fe_m[i];
    __shared__ double red[8];
    #pragma unroll
    for (int off = 16; off; off >>= 1) s += __shfl_down_sync(0xffffffffu, s, off);
    if ((tid & 31) == 0) red[tid >> 5] = s;
    __syncthreads();
    if (tid == 0) {
        double t = 0.0;
        #pragma unroll
        for (int w = 0; w < 8; w++) t += red[w];
        out[0] = (float)(t / (double)NB);
    }
}

// ---------------------------------------------------------------------------
// Host orchestration
// ---------------------------------------------------------------------------
static void host_split_keys(uint32_t& sk0, uint32_t& sk1,
                            uint32_t* ck0, uint32_t* ck1)
{
    uint32_t rk0 = 0u, rk1 = 42u;
    uint32_t c0, c1;
    threefry(rk0, rk1, 0u, 0u, c0, c1);    // k_chain
    threefry(rk0, rk1, 0u, 1u, sk0, sk1);  // k_start
    uint32_t k0 = c0, k1 = c1;
    for (int s = 0; s < NSTEPS; s++) {
        uint32_t nk0, nk1, h0, h1, v0, v1;
        threefry(k0, k1, 0u, 0u, nk0, nk1);
        threefry(k0, k1, 0u, 1u, h0, h1);  // kh
        threefry(k0, k1, 0u, 2u, v0, v1);  // kv
        ck0[2 * s] = h0;     ck1[2 * s] = h1;
        ck0[2 * s + 1] = v0; ck1[2 * s + 1] = v1;
        k0 = nk0; k1 = nk1;
    }
}

extern "C" void kernel_launch(void* const* d_in, const int* in_sizes, int n_in,
                              void* d_out, int out_size)
{
    const float* v_data = (const float*)d_in[0];
    const float* cond   = (const float*)d_in[1];
    const float* W      = (const float*)d_in[2];
    const float* b      = (const float*)d_in[3];
    const float* c      = (const float*)d_in[4];
    const float* W1     = (const float*)d_in[5];
    const float* b1     = (const float*)d_in[6];
    const float* W2     = (const float*)d_in[7];
    const float* b2     = (const float*)d_in[8];
    float* out = (float*)d_out;

    uint32_t sk0, sk1;
    uint32_t ck0[NCHAIN], ck1[NCHAIN];
    host_split_keys(sk0, sk1, ck0, ck1);

    cudaFuncSetAttribute(chain_step_kernel, cudaFuncAttributeMaxDynamicSharedMemorySize, CH_SMEM);
    cudaFuncSetAttribute(fe_kernel, cudaFuncAttributeMaxDynamicSharedMemorySize, FE_SMEM);

    uint16_t *p_v, *p_h, *p_Wh, *p_WTh, *p_WTb1, *p_WTb2, *p_vbf, *p_vdbf;
    float *p_bmod, *p_cmod, *p_fed, *p_fem, *p_fpd, *p_fpm;
    cudaGetSymbolAddress((void**)&p_v, g_v);
    cudaGetSymbolAddress((void**)&p_h, g_h);
    cudaGetSymbolAddress((void**)&p_vbf, g_v_bf);
    cudaGetSymbolAddress((void**)&p_vdbf, g_vd_bf);
    cudaGetSymbolAddress((void**)&p_Wh, g_Wh);
    cudaGetSymbolAddress((void**)&p_WTh, g_WTh);
    cudaGetSymbolAddress((void**)&p_WTb1, g_WTb1);
    cudaGetSymbolAddress((void**)&p_WTb2, g_WTb2);
    cudaGetSymbolAddress((void**)&p_bmod, g_bmod);
    cudaGetSymbolAddress((void**)&p_cmod, g_cmod);
    cudaGetSymbolAddress((void**)&p_fed, g_fe_d);
    cudaGetSymbolAddress((void**)&p_fem, g_fe_m);
    cudaGetSymbolAddress((void**)&p_fpd, g_fep_d);
    cudaGetSymbolAddress((void**)&p_fpm, g_fep_m);

    // Setup
    split_kernel<<<dim3(32, 32), dim3(32, 8)>>>(W);
    params_kernel<<<NB / PROWS, 256>>>(cond, b, c, W1, b1, W2, b2);
    init_v_kernel<<<(NB * NV) / 256, 256>>>(sk0, sk1);
    conv_vdata_kernel<<<(NB * NV) / 256, 256>>>(v_data);

    // Gibbs chain: 50 GEMM steps (register-direct epilogue)
    dim3 ggrid(8, 128);
    for (int s = 0; s < NCHAIN; s++) {
        const int even = !(s & 1);
        chain_step_kernel<<<ggrid, 256, CH_SMEM>>>(
            even ? p_v : p_h,
            even ? p_WTh : p_Wh,
            even ? p_cmod : p_bmod,
            even ? p_h : p_v,
            ck0[s], ck1[s]);
    }

    // Free energy
    conv_vmodel_kernel<<<(NB * NV) / 256, 256>>>();
    fe_kernel<<<ggrid, 256, FE_SMEM>>>(p_vdbf, p_WTb1, p_WTb2, p_cmod, p_fpd);
    fe_kernel<<<ggrid, 256, FE_SMEM>>>(p_vbf, p_WTb1, p_WTb2, p_cmod, p_fpm);
    rowdot_kernel<<<NB, 256>>>((const __nv_bfloat16*)p_vdbf, p_bmod, p_fpd, p_fed);
    rowdot_kernel<<<NB, 256>>>((const __nv_bfloat16*)p_vbf, p_bmod, p_fpm, p_fem);
    final_kernel<<<1, 256>>>(out);
}

// round 10
// speedup vs baseline: 1.3086x; 1.0310x over previous
#include <cuda_runtime.h>
#include <cuda_fp16.h>
#include <cstdint>

#define NB 16384
#define NV 1024
#define NH 1024
#define NC 64
#define NSTEPS 25
#define NCHAIN (2 * NSTEPS)

// ---------------------------------------------------------------------------
// Scratch (static __device__ allocations; no cudaMalloc anywhere)
// ---------------------------------------------------------------------------
__device__ float g_bmod[NB * NV];               // 64 MB
__device__ float g_cmod[NB * NH];               // 64 MB
__device__ __half g_v[NB * NV];                 // 32 MB (current v, 0/1 fp16)
__device__ __half g_h[NB * NH];                 // 32 MB
__device__ __half g_vd[NB * NV];                // 32 MB (v_data fp16, exact 0/1)
__device__ __half g_Wh[NV * NH];                // W fp16 [V][H]
__device__ __half g_WTh[NH * NV];               // W^T fp16 [H][V]
__device__ float g_fe_d[NB];
__device__ float g_fe_m[NB];
__device__ float g_fep_d[NB * 16];
__device__ float g_fep_m[NB * 16];

// ---------------------------------------------------------------------------
// threefry2x32 (exact JAX semantics, jax_threefry_partitionable)
// ---------------------------------------------------------------------------
__host__ __device__ __forceinline__ void threefry(uint32_t k0, uint32_t k1,
                                                  uint32_t x0, uint32_t x1,
                                                  uint32_t& o0, uint32_t& o1)
{
    uint32_t ks2 = k0 ^ k1 ^ 0x1BD11BDAu;
#define TF_ROT(x, r) (((x) << (r)) | ((x) >> (32 - (r))))
#define TF_RND(r) { x0 += x1; x1 = TF_ROT(x1, r); x1 ^= x0; }
    x0 += k0; x1 += k1;
    TF_RND(13) TF_RND(15) TF_RND(26) TF_RND(6)
    x0 += k1; x1 += ks2 + 1u;
    TF_RND(17) TF_RND(29) TF_RND(16) TF_RND(24)
    x0 += ks2; x1 += k0 + 2u;
    TF_RND(13) TF_RND(15) TF_RND(26) TF_RND(6)
    x0 += k0; x1 += k1 + 3u;
    TF_RND(17) TF_RND(29) TF_RND(16) TF_RND(24)
    x0 += k1; x1 += ks2 + 4u;
    TF_RND(13) TF_RND(15) TF_RND(26) TF_RND(6)
    x0 += ks2; x1 += k0 + 5u;
    o0 = x0; o1 = x1;
#undef TF_RND
#undef TF_ROT
}

__device__ __forceinline__ float urand(uint32_t k0, uint32_t k1, uint32_t idx)
{
    uint32_t a, b;
    threefry(k0, k1, 0u, idx, a, b);
    uint32_t bits = a ^ b;
    return __uint_as_float((bits >> 9) | 0x3F800000u) - 1.0f;
}

// ---------------------------------------------------------------------------
// MMA / ldmatrix / cp.async helpers (baseline PTX, legal on plain sm_103)
// ---------------------------------------------------------------------------
__device__ __forceinline__ uint32_t smem_u32(const void* p) {
    uint32_t a;
    asm("{ .reg .u64 t; cvta.to.shared.u64 t, %1; cvt.u32.u64 %0, t; }" : "=r"(a) : "l"(p));
    return a;
}
__device__ __forceinline__ void ldsm4(uint32_t* r, uint32_t addr) {
    asm volatile("ldmatrix.sync.aligned.m8n8.x4.shared.b16 {%0,%1,%2,%3}, [%4];"
                 : "=r"(r[0]), "=r"(r[1]), "=r"(r[2]), "=r"(r[3]) : "r"(addr));
}
__device__ __forceinline__ void mma_f16(float* d, const uint32_t* a, uint32_t b0, uint32_t b1) {
    asm volatile("mma.sync.aligned.m16n8k16.row.col.f32.f16.f16.f32 "
                 "{%0,%1,%2,%3}, {%4,%5,%6,%7}, {%8,%9}, {%0,%1,%2,%3};"
                 : "+f"(d[0]), "+f"(d[1]), "+f"(d[2]), "+f"(d[3])
                 : "r"(a[0]), "r"(a[1]), "r"(a[2]), "r"(a[3]), "r"(b0), "r"(b1));
}
#define CP_ASYNC16(dst, src) \
    asm volatile("cp.async.cg.shared.global [%0], [%1], 16;" :: "r"(dst), "l"(src))
#define CP_COMMIT() asm volatile("cp.async.commit_group;")
#define CP_WAIT1()  asm volatile("cp.async.wait_group 1;")
#define CP_WAIT0()  asm volatile("cp.async.wait_group 0;")

__device__ __forceinline__ uint32_t swz(uint32_t off) {  // SW128 on 128B rows
    return off ^ ((off >> 3) & 0x70);
}

// ---------------------------------------------------------------------------
// W -> fp16 plane, both orientations
// ---------------------------------------------------------------------------
__global__ void split_kernel(const float* __restrict__ W)
{
    __shared__ __half tf[32][33];
    int bx = blockIdx.x * 32;   // h
    int by = blockIdx.y * 32;   // v
    int tx = threadIdx.x, ty = threadIdx.y;  // 32 x 8
    #pragma unroll
    for (int i = 0; i < 32; i += 8) {
        float w = W[(size_t)(by + ty + i) * NH + bx + tx];
        __half hf = __float2half(w);
        g_Wh[(size_t)(by + ty + i) * NH + bx + tx] = hf;
        tf[ty + i][tx] = hf;
    }
    __syncthreads();
    #pragma unroll
    for (int i = 0; i < 32; i += 8)
        g_WTh[(size_t)(bx + ty + i) * NV + by + tx] = tf[tx][ty + i];
}

// ---------------------------------------------------------------------------
// Conditioning MLP -> b_mod, c_mod  (16 rows per block)
// ---------------------------------------------------------------------------
#define PROWS 16
__global__ void params_kernel(const float* __restrict__ cond, const float* __restrict__ b,
                              const float* __restrict__ c, const float* __restrict__ W1,
                              const float* __restrict__ b1, const float* __restrict__ W2,
                              const float* __restrict__ b2)
{
    __shared__ float sc[PROWS][NC];
    __shared__ float st[PROWS][NC];
    int row0 = blockIdx.x * PROWS;
    int tid = threadIdx.x;  // 256

    for (int i = tid; i < PROWS * NC; i += 256)
        sc[i / NC][i % NC] = cond[(size_t)(row0 + i / NC) * NC + (i % NC)];
    __syncthreads();
    for (int i = tid; i < PROWS * NC; i += 256) {
        int r = i / NC, j = i % NC;
        float s = b1[j];
        #pragma unroll 8
        for (int k = 0; k < NC; k++) s += sc[r][k] * W1[k * NC + j];
        st[r][j] = tanhf(s);
    }
    __syncthreads();

    for (int q = tid; q < NV; q += 256) {
        float ga[PROWS], be[PROWS];
        float ig = b2[q], ib = b2[NV + q];
        #pragma unroll
        for (int r = 0; r < PROWS; r++) { ga[r] = ig; be[r] = ib; }
        for (int k = 0; k < NC; k++) {
            float wg = W2[(size_t)k * 4096 + q];
            float wb = W2[(size_t)k * 4096 + NV + q];
            #pragma unroll
            for (int r = 0; r < PROWS; r++) { ga[r] += st[r][k] * wg; be[r] += st[r][k] * wb; }
        }
        float bq = b[q];
        #pragma unroll
        for (int r = 0; r < PROWS; r++)
            g_bmod[(size_t)(row0 + r) * NV + q] = (1.0f + ga[r]) * bq + be[r];
    }
    for (int q = tid; q < NH; q += 256) {
        float ga[PROWS], be[PROWS];
        float ig = b2[2 * NV + q], ib = b2[2 * NV + NH + q];
        #pragma unroll
        for (int r = 0; r < PROWS; r++) { ga[r] = ig; be[r] = ib; }
        for (int k = 0; k < NC; k++) {
            float wg = W2[(size_t)k * 4096 + 2 * NV + q];
            float wb = W2[(size_t)k * 4096 + 2 * NV + NH + q];
            #pragma unroll
            for (int r = 0; r < PROWS; r++) { ga[r] += st[r][k] * wg; be[r] += st[r][k] * wb; }
        }
        float cq = c[q];
        #pragma unroll
        for (int r = 0; r < PROWS; r++)
            g_cmod[(size_t)(row0 + r) * NH + q] = (1.0f + ga[r]) * cq + be[r];
    }
}

// ---------------------------------------------------------------------------
// init / conversion kernels
// ---------------------------------------------------------------------------
__global__ void init_v_kernel(uint32_t k0, uint32_t k1)
{
    uint32_t i = blockIdx.x * blockDim.x + threadIdx.x;
    float u = urand(k0, k1, i);
    ((uint16_t*)g_v)[i] = (u < 0.5f) ? 0x3C00u : 0u;   // fp16 1.0 / 0.0
}
__global__ void conv_vdata_kernel(const float* __restrict__ vd)
{
    uint32_t i = blockIdx.x * blockDim.x + threadIdx.x;
    g_vd[i] = __float2half(vd[i]);   // v_data is 0/1, exact in fp16
}

// ---------------------------------------------------------------------------
// Fused GEMM (fp16 single plane): Z[128x128 tile] = A @ B^T + bias
//   MODE 0: Out(fp16) = bernoulli(sigmoid(Z))
//   MODE 1: fe_part[row*16 + bx*2 + half] = sum_{64 cols} softplus(Z)
// 2-stage cp.async, K-chunk 64, warps 2(M)x4(N), z-spill + coalesced epilogue.
// ---------------------------------------------------------------------------
#define CH_STAGE 32768
#define ZSPILL_BYTES (128 * 132 * 4)   // 67584
#define CH_SMEM ((2 * CH_STAGE > ZSPILL_BYTES) ? 2 * CH_STAGE : ZSPILL_BYTES)  // 67584

__device__ __forceinline__ void ch_stage_load(uint32_t s_stage,
    const uint16_t* A, const uint16_t* B, int m0, int n0, int kk, int tid)
{
    #pragma unroll
    for (int r = 0; r < 8; r++) {
        int i = tid + r * 256;          // 0..2047
        int buf = i >> 10;              // 0:A 1:B
        int row = (i >> 3) & 127;
        int ch  = i & 7;
        const char* src = buf == 0
            ? (const char*)A + (size_t)(m0 + row) * 2048 + kk * 128 + ch * 16
            : (const char*)B + (size_t)(n0 + row) * 2048 + kk * 128 + ch * 16;
        uint32_t off = (uint32_t)(row * 128 + ch * 16);
        CP_ASYNC16(s_stage + buf * 16384 + swz(off), src);
    }
    CP_COMMIT();
}

template <int MODE>
__global__ void __launch_bounds__(256, 2)
gemm_kernel(const uint16_t* __restrict__ A, const uint16_t* __restrict__ B,
            const float* __restrict__ bias, uint16_t* __restrict__ Out,
            float* __restrict__ fe_part, uint32_t k0, uint32_t k1)
{
    extern __shared__ char smem[];
    const uint32_t sbase = smem_u32(smem);
    const int tid = threadIdx.x;
    const int wid = tid >> 5, lane = tid & 31;
    const int warp_m = wid & 1, warp_n = wid >> 1;
    const int la = lane & 15, ha = lane >> 4;
    const int m0 = blockIdx.y * 128;
    const int n0 = blockIdx.x * 128;

    float acc[4][4][4];                  // [mt(16m)][n8][frag]
    #pragma unroll
    for (int i = 0; i < 4; i++)
        #pragma unroll
        for (int j = 0; j < 4; j++)
            #pragma unroll
            for (int q = 0; q < 4; q++) acc[i][j][q] = 0.0f;

    ch_stage_load(sbase, A, B, m0, n0, 0, tid);

    #pragma unroll 1
    for (int kk = 0; kk < 16; kk++) {
        const uint32_t s = sbase + (uint32_t)(kk & 1) * CH_STAGE;
        if (kk + 1 < 16) {
            ch_stage_load(sbase + (uint32_t)((kk + 1) & 1) * CH_STAGE, A, B, m0, n0, kk + 1, tid);
            CP_WAIT1();
        } else {
            CP_WAIT0();
        }
        __syncthreads();

        #pragma unroll
        for (int ks = 0; ks < 4; ks++) {
            uint32_t a[4][4];
            #pragma unroll
            for (int mt = 0; mt < 4; mt++) {
                uint32_t off = (uint32_t)((warp_m * 64 + mt * 16 + la) * 128 + ks * 32 + ha * 16);
                ldsm4(a[mt], s + swz(off));
            }
            uint32_t b[2][4];
            #pragma unroll
            for (int g = 0; g < 2; g++) {
                uint32_t off = (uint32_t)((warp_n * 32 + g * 16 + la) * 128 + ks * 32 + ha * 16);
                ldsm4(b[g], s + 16384u + swz(off));
            }
            #pragma unroll
            for (int mt = 0; mt < 4; mt++)
                #pragma unroll
                for (int n8 = 0; n8 < 4; n8++)
                    mma_f16(acc[mt][n8], a[mt], b[n8 >> 1][n8 & 1], b[n8 >> 1][(n8 & 1) + 2]);
        }
        __syncthreads();
    }

    // Spill Z to smem (stride 132 floats)
    float* zs = (float*)smem;
    #pragma unroll
    for (int mt = 0; mt < 4; mt++)
        #pragma unroll
        for (int n8 = 0; n8 < 4; n8++) {
            int r = warp_m * 64 + mt * 16 + (lane >> 2);
            int cc = warp_n * 32 + n8 * 8 + (lane & 3) * 2;
            zs[r * 132 + cc]           = acc[mt][n8][0];
            zs[r * 132 + cc + 1]       = acc[mt][n8][1];
            zs[(r + 8) * 132 + cc]     = acc[mt][n8][2];
            zs[(r + 8) * 132 + cc + 1] = acc[mt][n8][3];
        }
    __syncthreads();

    // Per-thread epilogue: row = tid>>1 (local), 64-col half = tid&1
    const int rloc = tid >> 1;
    const int c0 = (tid & 1) * 64;
    const int row = m0 + rloc;
    const float* zrow = zs + rloc * 132 + c0;
    const float4* bp = (const float4*)(bias + (size_t)row * 1024 + n0 + c0);

    if (MODE == 0) {
        const uint32_t ibase = (uint32_t)(row * 1024 + n0 + c0);
        uint4* op = (uint4*)(Out + (size_t)row * 1024 + n0 + c0);
        #pragma unroll 1
        for (int j0 = 0; j0 < 64; j0 += 8) {
            float4 bv0 = bp[j0 / 4], bv1 = bp[j0 / 4 + 1];
            float zb[8] = {bv0.x, bv0.y, bv0.z, bv0.w, bv1.x, bv1.y, bv1.z, bv1.w};
            uint32_t pk[4];
            #pragma unroll
            for (int jj = 0; jj < 8; jj += 2) {
                float z0 = zrow[j0 + jj] + zb[jj];
                float z1 = zrow[j0 + jj + 1] + zb[jj + 1];
                float e0 = __expf(-z0), e1 = __expf(-z1);
                float u0 = urand(k0, k1, ibase + (uint32_t)(j0 + jj));
                float u1 = urand(k0, k1, ibase + (uint32_t)(j0 + jj) + 1u);
                uint32_t s0 = (fmaf(u0, e0, u0) < 1.0f) ? 0x3C00u : 0u;  // fp16 1.0
                uint32_t s1 = (fmaf(u1, e1, u1) < 1.0f) ? 0x3C00u : 0u;
                pk[jj >> 1] = s0 | (s1 << 16);
            }
            op[j0 / 8] = make_uint4(pk[0], pk[1], pk[2], pk[3]);
        }
    } else {
        float sp_acc = 0.0f;
        #pragma unroll 1
        for (int j0 = 0; j0 < 64; j0 += 8) {
            float4 bv0 = bp[j0 / 4], bv1 = bp[j0 / 4 + 1];
            float zb[8] = {bv0.x, bv0.y, bv0.z, bv0.w, bv1.x, bv1.y, bv1.z, bv1.w};
            #pragma unroll
            for (int jj = 0; jj < 8; jj++) {
                float z = zrow[j0 + jj] + zb[jj];
                sp_acc += fmaxf(z, 0.0f) + log1pf(expf(-fabsf(z)));
            }
        }
        fe_part[(size_t)row * 16 + blockIdx.x * 2 + (tid & 1)] = sp_acc;
    }
}

// ---------------------------------------------------------------------------
// fe[row] = -(v . bmod_row) - sum(fe_part[row, :16])   (fp16 v)
// ---------------------------------------------------------------------------
__global__ void rowdot_kernel(const __half* __restrict__ v, const float* __restrict__ bmod,
                              const float* __restrict__ part, float* __restrict__ fe)
{
    int row = blockIdx.x;
    int tid = threadIdx.x;  // 256
    float s = 0.0f;
    for (int q = tid; q < NV; q += 256)
        s += __half2float(v[(size_t)row * NV + q]) * bmod[(size_t)row * NV + q];
    __shared__ float red[8];
    #pragma unroll
    for (int off = 16; off; off >>= 1) s += __shfl_down_sync(0xffffffffu, s, off);
    if ((tid & 31) == 0) red[tid >> 5] = s;
    __syncthreads();
    if (tid == 0) {
        float dsum = 0.0f;
        #pragma unroll
        for (int w = 0; w < 8; w++) dsum += red[w];
        float sp = 0.0f;
        #pragma unroll
        for (int j = 0; j < 16; j++) sp += part[(size_t)row * 16 + j];
        fe[row] = -dsum - sp;
    }
}

__global__ void final_kernel(float* __restrict__ out)
{
    int tid = threadIdx.x;  // 256
    double s = 0.0;
    for (int i = tid; i < NB; i += 256)
        s += (double)g_fe_d[i] - (double)g_fe_m[i];
    __shared__ double red[8];
    #pragma unroll
    for (int off = 16; off; off >>= 1) s += __shfl_down_sync(0xffffffffu, s, off);
    if ((tid & 31) == 0) red[tid >> 5] = s;
    __syncthreads();
    if (tid == 0) {
        double t = 0.0;
        #pragma unroll
        for (int w = 0; w < 8; w++) t += red[w];
        out[0] = (float)(t / (double)NB);
    }
}

// ---------------------------------------------------------------------------
// Host orchestration
// ---------------------------------------------------------------------------
static void host_split_keys(uint32_t& sk0, uint32_t& sk1,
                            uint32_t* ck0, uint32_t* ck1)
{
    uint32_t rk0 = 0u, rk1 = 42u;
    uint32_t c0, c1;
    threefry(rk0, rk1, 0u, 0u, c0, c1);    // k_chain
    threefry(rk0, rk1, 0u, 1u, sk0, sk1);  // k_start
    uint32_t k0 = c0, k1 = c1;
    for (int s = 0; s < NSTEPS; s++) {
        uint32_t nk0, nk1, h0, h1, v0, v1;
        threefry(k0, k1, 0u, 0u, nk0, nk1);
        threefry(k0, k1, 0u, 1u, h0, h1);  // kh
        threefry(k0, k1, 0u, 2u, v0, v1);  // kv
        ck0[2 * s] = h0;     ck1[2 * s] = h1;
        ck0[2 * s + 1] = v0; ck1[2 * s + 1] = v1;
        k0 = nk0; k1 = nk1;
    }
}

extern "C" void kernel_launch(void* const* d_in, const int* in_sizes, int n_in,
                              void* d_out, int out_size)
{
    const float* v_data = (const float*)d_in[0];
    const float* cond   = (const float*)d_in[1];
    const float* W      = (const float*)d_in[2];
    const float* b      = (const float*)d_in[3];
    const float* c      = (const float*)d_in[4];
    const float* W1     = (const float*)d_in[5];
    const float* b1     = (const float*)d_in[6];
    const float* W2     = (const float*)d_in[7];
    const float* b2     = (const float*)d_in[8];
    float* out = (float*)d_out;

    uint32_t sk0, sk1;
    uint32_t ck0[NCHAIN], ck1[NCHAIN];
    host_split_keys(sk0, sk1, ck0, ck1);

    cudaFuncSetAttribute(gemm_kernel<0>, cudaFuncAttributeMaxDynamicSharedMemorySize, CH_SMEM);
    cudaFuncSetAttribute(gemm_kernel<1>, cudaFuncAttributeMaxDynamicSharedMemorySize, CH_SMEM);

    uint16_t *p_v, *p_h, *p_vd, *p_Wh, *p_WTh;
    float *p_bmod, *p_cmod, *p_fed, *p_fem, *p_fpd, *p_fpm;
    cudaGetSymbolAddress((void**)&p_v, g_v);
    cudaGetSymbolAddress((void**)&p_h, g_h);
    cudaGetSymbolAddress((void**)&p_vd, g_vd);
    cudaGetSymbolAddress((void**)&p_Wh, g_Wh);
    cudaGetSymbolAddress((void**)&p_WTh, g_WTh);
    cudaGetSymbolAddress((void**)&p_bmod, g_bmod);
    cudaGetSymbolAddress((void**)&p_cmod, g_cmod);
    cudaGetSymbolAddress((void**)&p_fed, g_fe_d);
    cudaGetSymbolAddress((void**)&p_fem, g_fe_m);
    cudaGetSymbolAddress((void**)&p_fpd, g_fep_d);
    cudaGetSymbolAddress((void**)&p_fpm, g_fep_m);

    // Setup
    split_kernel<<<dim3(32, 32), dim3(32, 8)>>>(W);
    params_kernel<<<NB / PROWS, 256>>>(cond, b, c, W1, b1, W2, b2);
    init_v_kernel<<<(NB * NV) / 256, 256>>>(sk0, sk1);
    conv_vdata_kernel<<<(NB * NV) / 256, 256>>>(v_data);

    // Gibbs chain: 50 GEMM steps (identical to R6 chain)
    dim3 ggrid(8, 128);
    for (int s = 0; s < NCHAIN; s++) {
        const int even = !(s & 1);
        gemm_kernel<0><<<ggrid, 256, CH_SMEM>>>(
            even ? p_v : p_h,
            even ? p_WTh : p_Wh,
            even ? p_cmod : p_bmod,
            even ? p_h : p_v,
            nullptr, ck0[s], ck1[s]);
    }

    // Free energy (fp16 single plane; v_model used directly)
    gemm_kernel<1><<<ggrid, 256, CH_SMEM>>>(p_vd, p_WTh, p_cmod, nullptr, p_fpd, 0u, 0u);
    gemm_kernel<1><<<ggrid, 256, CH_SMEM>>>(p_v,  p_WTh, p_cmod, nullptr, p_fpm, 0u, 0u);
    rowdot_kernel<<<NB, 256>>>((const __half*)p_vd, p_bmod, p_fpd, p_fed);
    rowdot_kernel<<<NB, 256>>>((const __half*)p_v,  p_bmod, p_fpm, p_fem);
    final_kernel<<<1, 256>>>(out);
}

// round 11
// speedup vs baseline: 1.4072x; 1.0754x over previous
#include <cuda_runtime.h>
#include <cuda_fp16.h>
#include <cstdint>

#define NB 16384
#define NV 1024
#define NH 1024
#define NC 64
#define NSTEPS 25
#define NCHAIN (2 * NSTEPS)
#define HALF_B (NB / 2)

// ---------------------------------------------------------------------------
// Scratch (static __device__ allocations; no cudaMalloc anywhere)
// ---------------------------------------------------------------------------
__device__ float g_bmod[NB * NV];               // 64 MB
__device__ float g_cmod[NB * NH];               // 64 MB
__device__ __half g_v[NB * NV];                 // 32 MB (current v, 0/1 fp16)
__device__ __half g_h[NB * NH];                 // 32 MB
__device__ __half g_vd[NB * NV];                // 32 MB (v_data fp16, exact 0/1)
__device__ __half g_Wh[NV * NH];                // W fp16 [V][H]
__device__ __half g_WTh[NH * NV];               // W^T fp16 [H][V]
__device__ float g_fe_d[NB];
__device__ float g_fe_m[NB];
__device__ float g_fep_d[NB * 16];
__device__ float g_fep_m[NB * 16];

// ---------------------------------------------------------------------------
// threefry2x32 (exact JAX semantics, jax_threefry_partitionable)
// ---------------------------------------------------------------------------
__host__ __device__ __forceinline__ void threefry(uint32_t k0, uint32_t k1,
                                                  uint32_t x0, uint32_t x1,
                                                  uint32_t& o0, uint32_t& o1)
{
    uint32_t ks2 = k0 ^ k1 ^ 0x1BD11BDAu;
#define TF_ROT(x, r) (((x) << (r)) | ((x) >> (32 - (r))))
#define TF_RND(r) { x0 += x1; x1 = TF_ROT(x1, r); x1 ^= x0; }
    x0 += k0; x1 += k1;
    TF_RND(13) TF_RND(15) TF_RND(26) TF_RND(6)
    x0 += k1; x1 += ks2 + 1u;
    TF_RND(17) TF_RND(29) TF_RND(16) TF_RND(24)
    x0 += ks2; x1 += k0 + 2u;
    TF_RND(13) TF_RND(15) TF_RND(26) TF_RND(6)
    x0 += k0; x1 += k1 + 3u;
    TF_RND(17) TF_RND(29) TF_RND(16) TF_RND(24)
    x0 += k1; x1 += ks2 + 4u;
    TF_RND(13) TF_RND(15) TF_RND(26) TF_RND(6)
    x0 += ks2; x1 += k0 + 5u;
    o0 = x0; o1 = x1;
#undef TF_RND
#undef TF_ROT
}

__device__ __forceinline__ float urand(uint32_t k0, uint32_t k1, uint32_t idx)
{
    uint32_t a, b;
    threefry(k0, k1, 0u, idx, a, b);
    uint32_t bits = a ^ b;
    return __uint_as_float((bits >> 9) | 0x3F800000u) - 1.0f;
}

// ---------------------------------------------------------------------------
// MMA / ldmatrix / cp.async helpers (baseline PTX, legal on plain sm_103)
// ---------------------------------------------------------------------------
__device__ __forceinline__ uint32_t smem_u32(const void* p) {
    uint32_t a;
    asm("{ .reg .u64 t; cvta.to.shared.u64 t, %1; cvt.u32.u64 %0, t; }" : "=r"(a) : "l"(p));
    return a;
}
__device__ __forceinline__ void ldsm4(uint32_t* r, uint32_t addr) {
    asm volatile("ldmatrix.sync.aligned.m8n8.x4.shared.b16 {%0,%1,%2,%3}, [%4];"
                 : "=r"(r[0]), "=r"(r[1]), "=r"(r[2]), "=r"(r[3]) : "r"(addr));
}
__device__ __forceinline__ void mma_f16(float* d, const uint32_t* a, uint32_t b0, uint32_t b1) {
    asm volatile("mma.sync.aligned.m16n8k16.row.col.f32.f16.f16.f32 "
                 "{%0,%1,%2,%3}, {%4,%5,%6,%7}, {%8,%9}, {%0,%1,%2,%3};"
                 : "+f"(d[0]), "+f"(d[1]), "+f"(d[2]), "+f"(d[3])
                 : "r"(a[0]), "r"(a[1]), "r"(a[2]), "r"(a[3]), "r"(b0), "r"(b1));
}
#define CP_ASYNC16(dst, src) \
    asm volatile("cp.async.cg.shared.global [%0], [%1], 16;" :: "r"(dst), "l"(src))
#define CP_COMMIT() asm volatile("cp.async.commit_group;")
#define CP_WAIT1()  asm volatile("cp.async.wait_group 1;")
#define CP_WAIT0()  asm volatile("cp.async.wait_group 0;")

__device__ __forceinline__ uint32_t swz(uint32_t off) {  // SW128 on 128B rows
    return off ^ ((off >> 3) & 0x70);
}

// ---------------------------------------------------------------------------
// W -> fp16 plane, both orientations
// ---------------------------------------------------------------------------
__global__ void split_kernel(const float* __restrict__ W)
{
    __shared__ __half tf[32][33];
    int bx = blockIdx.x * 32;   // h
    int by = blockIdx.y * 32;   // v
    int tx = threadIdx.x, ty = threadIdx.y;  // 32 x 8
    #pragma unroll
    for (int i = 0; i < 32; i += 8) {
        float w = W[(size_t)(by + ty + i) * NH + bx + tx];
        __half hf = __float2half(w);
        g_Wh[(size_t)(by + ty + i) * NH + bx + tx] = hf;
        tf[ty + i][tx] = hf;
    }
    __syncthreads();
    #pragma unroll
    for (int i = 0; i < 32; i += 8)
        g_WTh[(size_t)(bx + ty + i) * NV + by + tx] = tf[tx][ty + i];
}

// ---------------------------------------------------------------------------
// Conditioning MLP -> b_mod, c_mod  (16 rows per block)
// ---------------------------------------------------------------------------
#define PROWS 16
__global__ void params_kernel(const float* __restrict__ cond, const float* __restrict__ b,
                              const float* __restrict__ c, const float* __restrict__ W1,
                              const float* __restrict__ b1, const float* __restrict__ W2,
                              const float* __restrict__ b2)
{
    __shared__ float sc[PROWS][NC];
    __shared__ float st[PROWS][NC];
    int row0 = blockIdx.x * PROWS;
    int tid = threadIdx.x;  // 256

    for (int i = tid; i < PROWS * NC; i += 256)
        sc[i / NC][i % NC] = cond[(size_t)(row0 + i / NC) * NC + (i % NC)];
    __syncthreads();
    for (int i = tid; i < PROWS * NC; i += 256) {
        int r = i / NC, j = i % NC;
        float s = b1[j];
        #pragma unroll 8
        for (int k = 0; k < NC; k++) s += sc[r][k] * W1[k * NC + j];
        st[r][j] = tanhf(s);
    }
    __syncthreads();

    for (int q = tid; q < NV; q += 256) {
        float ga[PROWS], be[PROWS];
        float ig = b2[q], ib = b2[NV + q];
        #pragma unroll
        for (int r = 0; r < PROWS; r++) { ga[r] = ig; be[r] = ib; }
        for (int k = 0; k < NC; k++) {
            float wg = W2[(size_t)k * 4096 + q];
            float wb = W2[(size_t)k * 4096 + NV + q];
            #pragma unroll
            for (int r = 0; r < PROWS; r++) { ga[r] += st[r][k] * wg; be[r] += st[r][k] * wb; }
        }
        float bq = b[q];
        #pragma unroll
        for (int r = 0; r < PROWS; r++)
            g_bmod[(size_t)(row0 + r) * NV + q] = (1.0f + ga[r]) * bq + be[r];
    }
    for (int q = tid; q < NH; q += 256) {
        float ga[PROWS], be[PROWS];
        float ig = b2[2 * NV + q], ib = b2[2 * NV + NH + q];
        #pragma unroll
        for (int r = 0; r < PROWS; r++) { ga[r] = ig; be[r] = ib; }
        for (int k = 0; k < NC; k++) {
            float wg = W2[(size_t)k * 4096 + 2 * NV + q];
            float wb = W2[(size_t)k * 4096 + 2 * NV + NH + q];
            #pragma unroll
            for (int r = 0; r < PROWS; r++) { ga[r] += st[r][k] * wg; be[r] += st[r][k] * wb; }
        }
        float cq = c[q];
        #pragma unroll
        for (int r = 0; r < PROWS; r++)
            g_cmod[(size_t)(row0 + r) * NH + q] = (1.0f + ga[r]) * cq + be[r];
    }
}

// ---------------------------------------------------------------------------
// init / conversion kernels
// ---------------------------------------------------------------------------
__global__ void init_v_kernel(uint32_t k0, uint32_t k1)
{
    uint32_t i = blockIdx.x * blockDim.x + threadIdx.x;
    float u = urand(k0, k1, i);
    ((uint16_t*)g_v)[i] = (u < 0.5f) ? 0x3C00u : 0u;   // fp16 1.0 / 0.0
}
__global__ void conv_vdata_kernel(const float* __restrict__ vd)
{
    uint32_t i = blockIdx.x * blockDim.x + threadIdx.x;
    g_vd[i] = __float2half(vd[i]);   // v_data is 0/1, exact in fp16
}

// ---------------------------------------------------------------------------
// Fused GEMM (fp16 single plane): Z[128x128 tile] = A @ B^T + bias
//   MODE 0: Out(fp16) = bernoulli(sigmoid(Z)); RNG index = gbase + local idx
//   MODE 1: fe_part[row*16 + bx*2 + half] = sum_{64 cols} softplus(Z)
// 2-stage cp.async, K-chunk 64, warps 2(M)x4(N), z-spill + coalesced epilogue.
// All row indexing is relative to the passed pointers (caller offsets halves).
// ---------------------------------------------------------------------------
#define CH_STAGE 32768
#define ZSPILL_BYTES (128 * 132 * 4)   // 67584
#define CH_SMEM ((2 * CH_STAGE > ZSPILL_BYTES) ? 2 * CH_STAGE : ZSPILL_BYTES)  // 67584

__device__ __forceinline__ void ch_stage_load(uint32_t s_stage,
    const uint16_t* A, const uint16_t* B, int m0, int n0, int kk, int tid)
{
    #pragma unroll
    for (int r = 0; r < 8; r++) {
        int i = tid + r * 256;          // 0..2047
        int buf = i >> 10;              // 0:A 1:B
        int row = (i >> 3) & 127;
        int ch  = i & 7;
        const char* src = buf == 0
            ? (const char*)A + (size_t)(m0 + row) * 2048 + kk * 128 + ch * 16
            : (const char*)B + (size_t)(n0 + row) * 2048 + kk * 128 + ch * 16;
        uint32_t off = (uint32_t)(row * 128 + ch * 16);
        CP_ASYNC16(s_stage + buf * 16384 + swz(off), src);
    }
    CP_COMMIT();
}

template <int MODE>
__global__ void __launch_bounds__(256, 2)
gemm_kernel(const uint16_t* __restrict__ A, const uint16_t* __restrict__ B,
            const float* __restrict__ bias, uint16_t* __restrict__ Out,
            float* __restrict__ fe_part, uint32_t gbase, uint32_t k0, uint32_t k1)
{
    extern __shared__ char smem[];
    const uint32_t sbase = smem_u32(smem);
    const int tid = threadIdx.x;
    const int wid = tid >> 5, lane = tid & 31;
    const int warp_m = wid & 1, warp_n = wid >> 1;
    const int la = lane & 15, ha = lane >> 4;
    const int m0 = blockIdx.y * 128;
    const int n0 = blockIdx.x * 128;

    float acc[4][4][4];                  // [mt(16m)][n8][frag]
    #pragma unroll
    for (int i = 0; i < 4; i++)
        #pragma unroll
        for (int j = 0; j < 4; j++)
            #pragma unroll
            for (int q = 0; q < 4; q++) acc[i][j][q] = 0.0f;

    ch_stage_load(sbase, A, B, m0, n0, 0, tid);

    #pragma unroll 1
    for (int kk = 0; kk < 16; kk++) {
        const uint32_t s = sbase + (uint32_t)(kk & 1) * CH_STAGE;
        if (kk + 1 < 16) {
            ch_stage_load(sbase + (uint32_t)((kk + 1) & 1) * CH_STAGE, A, B, m0, n0, kk + 1, tid);
            CP_WAIT1();
        } else {
            CP_WAIT0();
        }
        __syncthreads();

        #pragma unroll
        for (int ks = 0; ks < 4; ks++) {
            uint32_t a[4][4];
            #pragma unroll
            for (int mt = 0; mt < 4; mt++) {
                uint32_t off = (uint32_t)((warp_m * 64 + mt * 16 + la) * 128 + ks * 32 + ha * 16);
                ldsm4(a[mt], s + swz(off));
            }
            uint32_t b[2][4];
            #pragma unroll
            for (int g = 0; g < 2; g++) {
                uint32_t off = (uint32_t)((warp_n * 32 + g * 16 + la) * 128 + ks * 32 + ha * 16);
                ldsm4(b[g], s + 16384u + swz(off));
            }
            #pragma unroll
            for (int mt = 0; mt < 4; mt++)
                #pragma unroll
                for (int n8 = 0; n8 < 4; n8++)
                    mma_f16(acc[mt][n8], a[mt], b[n8 >> 1][n8 & 1], b[n8 >> 1][(n8 & 1) + 2]);
        }
        __syncthreads();
    }

    // Spill Z to smem (stride 132 floats)
    float* zs = (float*)smem;
    #pragma unroll
    for (int mt = 0; mt < 4; mt++)
        #pragma unroll
        for (int n8 = 0; n8 < 4; n8++) {
            int r = warp_m * 64 + mt * 16 + (lane >> 2);
            int cc = warp_n * 32 + n8 * 8 + (lane & 3) * 2;
            zs[r * 132 + cc]           = acc[mt][n8][0];
            zs[r * 132 + cc + 1]       = acc[mt][n8][1];
            zs[(r + 8) * 132 + cc]     = acc[mt][n8][2];
            zs[(r + 8) * 132 + cc + 1] = acc[mt][n8][3];
        }
    __syncthreads();

    // Per-thread epilogue: row = tid>>1 (local), 64-col half = tid&1
    const int rloc = tid >> 1;
    const int c0 = (tid & 1) * 64;
    const int row = m0 + rloc;
    const float* zrow = zs + rloc * 132 + c0;
    const float4* bp = (const float4*)(bias + (size_t)row * 1024 + n0 + c0);

    if (MODE == 0) {
        const uint32_t ibase = gbase + (uint32_t)(row * 1024 + n0 + c0);
        uint4* op = (uint4*)(Out + (size_t)row * 1024 + n0 + c0);
        #pragma unroll 1
        for (int j0 = 0; j0 < 64; j0 += 8) {
            float4 bv0 = bp[j0 / 4], bv1 = bp[j0 / 4 + 1];
            float zb[8] = {bv0.x, bv0.y, bv0.z, bv0.w, bv1.x, bv1.y, bv1.z, bv1.w};
            uint32_t pk[4];
            #pragma unroll
            for (int jj = 0; jj < 8; jj += 2) {
                float z0 = zrow[j0 + jj] + zb[jj];
                float z1 = zrow[j0 + jj + 1] + zb[jj + 1];
                float e0 = __expf(-z0), e1 = __expf(-z1);
                float u0 = urand(k0, k1, ibase + (uint32_t)(j0 + jj));
                float u1 = urand(k0, k1, ibase + (uint32_t)(j0 + jj) + 1u);
                uint32_t s0 = (fmaf(u0, e0, u0) < 1.0f) ? 0x3C00u : 0u;  // fp16 1.0
                uint32_t s1 = (fmaf(u1, e1, u1) < 1.0f) ? 0x3C00u : 0u;
                pk[jj >> 1] = s0 | (s1 << 16);
            }
            op[j0 / 8] = make_uint4(pk[0], pk[1], pk[2], pk[3]);
        }
    } else {
        float sp_acc = 0.0f;
        #pragma unroll 1
        for (int j0 = 0; j0 < 64; j0 += 8) {
            float4 bv0 = bp[j0 / 4], bv1 = bp[j0 / 4 + 1];
            float zb[8] = {bv0.x, bv0.y, bv0.z, bv0.w, bv1.x, bv1.y, bv1.z, bv1.w};
            #pragma unroll
            for (int jj = 0; jj < 8; jj++) {
                float z = zrow[j0 + jj] + zb[jj];
                sp_acc += fmaxf(z, 0.0f) + log1pf(expf(-fabsf(z)));
            }
        }
        fe_part[(size_t)row * 16 + blockIdx.x * 2 + (tid & 1)] = sp_acc;
    }
}

// ---------------------------------------------------------------------------
// fe[row] = -(v . bmod_row) - sum(fe_part[row, :16])   (fp16 v)
// ---------------------------------------------------------------------------
__global__ void rowdot_kernel(const __half* __restrict__ v, const float* __restrict__ bmod,
                              const float* __restrict__ part, float* __restrict__ fe)
{
    int row = blockIdx.x;
    int tid = threadIdx.x;  // 256
    float s = 0.0f;
    for (int q = tid; q < NV; q += 256)
        s += __half2float(v[(size_t)row * NV + q]) * bmod[(size_t)row * NV + q];
    __shared__ float red[8];
    #pragma unroll
    for (int off = 16; off; off >>= 1) s += __shfl_down_sync(0xffffffffu, s, off);
    if ((tid & 31) == 0) red[tid >> 5] = s;
    __syncthreads();
    if (tid == 0) {
        float dsum = 0.0f;
        #pragma unroll
        for (int w = 0; w < 8; w++) dsum += red[w];
        float sp = 0.0f;
        #pragma unroll
        for (int j = 0; j < 16; j++) sp += part[(size_t)row * 16 + j];
        fe[row] = -dsum - sp;
    }
}

__global__ void final_kernel(float* __restrict__ out)
{
    int tid = threadIdx.x;  // 256
    double s = 0.0;
    for (int i = tid; i < NB; i += 256)
        s += (double)g_fe_d[i] - (double)g_fe_m[i];
    __shared__ double red[8];
    #pragma unroll
    for (int off = 16; off; off >>= 1) s += __shfl_down_sync(0xffffffffu, s, off);
    if ((tid & 31) == 0) red[tid >> 5] = s;
    __syncthreads();
    if (tid == 0) {
        double t = 0.0;
        #pragma unroll
        for (int w = 0; w < 8; w++) t += red[w];
        out[0] = (float)(t / (double)NB);
    }
}

// ---------------------------------------------------------------------------
// Host orchestration
// ---------------------------------------------------------------------------
static void host_split_keys(uint32_t& sk0, uint32_t& sk1,
                            uint32_t* ck0, uint32_t* ck1)
{
    uint32_t rk0 = 0u, rk1 = 42u;
    uint32_t c0, c1;
    threefry(rk0, rk1, 0u, 0u, c0, c1);    // k_chain
    threefry(rk0, rk1, 0u, 1u, sk0, sk1);  // k_start
    uint32_t k0 = c0, k1 = c1;
    for (int s = 0; s < NSTEPS; s++) {
        uint32_t nk0, nk1, h0, h1, v0, v1;
        threefry(k0, k1, 0u, 0u, nk0, nk1);
        threefry(k0, k1, 0u, 1u, h0, h1);  // kh
        threefry(k0, k1, 0u, 2u, v0, v1);  // kv
        ck0[2 * s] = h0;     ck1[2 * s] = h1;
        ck0[2 * s + 1] = v0; ck1[2 * s + 1] = v1;
        k0 = nk0; k1 = nk1;
    }
}

extern "C" void kernel_launch(void* const* d_in, const int* in_sizes, int n_in,
                              void* d_out, int out_size)
{
    const float* v_data = (const float*)d_in[0];
    const float* cond   = (const float*)d_in[1];
    const float* W      = (const float*)d_in[2];
    const float* b      = (const float*)d_in[3];
    const float* c      = (const float*)d_in[4];
    const float* W1     = (const float*)d_in[5];
    const float* b1     = (const float*)d_in[6];
    const float* W2     = (const float*)d_in[7];
    const float* b2     = (const float*)d_in[8];
    float* out = (float*)d_out;

    uint32_t sk0, sk1;
    uint32_t ck0[NCHAIN], ck1[NCHAIN];
    host_split_keys(sk0, sk1, ck0, ck1);

    // Streams/events created once on the (uncaptured) correctness call.
    static cudaStream_t sA = nullptr, sB = nullptr;
    static cudaEvent_t ev0 = nullptr, evA = nullptr, evB = nullptr;
    if (!sA) {
        cudaStreamCreateWithFlags(&sA, cudaStreamNonBlocking);
        cudaStreamCreateWithFlags(&sB, cudaStreamNonBlocking);
        cudaEventCreateWithFlags(&ev0, cudaEventDisableTiming);
        cudaEventCreateWithFlags(&evA, cudaEventDisableTiming);
        cudaEventCreateWithFlags(&evB, cudaEventDisableTiming);
    }

    cudaFuncSetAttribute(gemm_kernel<0>, cudaFuncAttributeMaxDynamicSharedMemorySize, CH_SMEM);
    cudaFuncSetAttribute(gemm_kernel<1>, cudaFuncAttributeMaxDynamicSharedMemorySize, CH_SMEM);

    uint16_t *p_v, *p_h, *p_vd, *p_Wh, *p_WTh;
    float *p_bmod, *p_cmod, *p_fed, *p_fem, *p_fpd, *p_fpm;
    cudaGetSymbolAddress((void**)&p_v, g_v);
    cudaGetSymbolAddress((void**)&p_h, g_h);
    cudaGetSymbolAddress((void**)&p_vd, g_vd);
    cudaGetSymbolAddress((void**)&p_Wh, g_Wh);
    cudaGetSymbolAddress((void**)&p_WTh, g_WTh);
    cudaGetSymbolAddress((void**)&p_bmod, g_bmod);
    cudaGetSymbolAddress((void**)&p_cmod, g_cmod);
    cudaGetSymbolAddress((void**)&p_fed, g_fe_d);
    cudaGetSymbolAddress((void**)&p_fem, g_fe_m);
    cudaGetSymbolAddress((void**)&p_fpd, g_fep_d);
    cudaGetSymbolAddress((void**)&p_fpm, g_fep_m);

    // Setup on the capture (default) stream
    split_kernel<<<dim3(32, 32), dim3(32, 8)>>>(W);
    params_kernel<<<NB / PROWS, 256>>>(cond, b, c, W1, b1, W2, b2);
    init_v_kernel<<<(NB * NV) / 256, 256>>>(sk0, sk1);
    conv_vdata_kernel<<<(NB * NV) / 256, 256>>>(v_data);

    // Fork: two independent half-batch chains
    cudaEventRecord(ev0, 0);
    cudaStreamWaitEvent(sA, ev0, 0);
    cudaStreamWaitEvent(sB, ev0, 0);

    const dim3 hgrid(8, HALF_B / 128);   // (8, 64)
    const uint32_t roff[2] = { 0u, (uint32_t)HALF_B };
    cudaStream_t streams[2] = { sA, sB };

    for (int half = 0; half < 2; half++) {
        const size_t eo = (size_t)roff[half] * 1024;    // element offset (rows x 1024)
        const uint32_t gb = roff[half] * 1024u;         // global RNG index base
        cudaStream_t st = streams[half];
        for (int s = 0; s < NCHAIN; s++) {
            const int even = !(s & 1);
            gemm_kernel<0><<<hgrid, 256, CH_SMEM, st>>>(
                (even ? p_v : p_h) + eo,
                even ? p_WTh : p_Wh,
                (even ? p_cmod : p_bmod) + eo,
                (even ? p_h : p_v) + eo,
                nullptr, gb, ck0[s], ck1[s]);
        }
        // Free energy for this half
        gemm_kernel<1><<<hgrid, 256, CH_SMEM, st>>>(
            p_vd + eo, p_WTh, p_cmod + eo, nullptr, p_fpd + (size_t)roff[half] * 16, 0u, 0u, 0u);
        gemm_kernel<1><<<hgrid, 256, CH_SMEM, st>>>(
            p_v + eo, p_WTh, p_cmod + eo, nullptr, p_fpm + (size_t)roff[half] * 16, 0u, 0u, 0u);
        rowdot_kernel<<<HALF_B, 256, 0, st>>>(
            (const __half*)(p_vd + eo), p_bmod + eo, p_fpd + (size_t)roff[half] * 16, p_fed + roff[half]);
        rowdot_kernel<<<HALF_B, 256, 0, st>>>(
            (const __half*)(p_v + eo), p_bmod + eo, p_fpm + (size_t)roff[half] * 16, p_fem + roff[half]);
    }

    // Join and reduce
    cudaEventRecord(evA, sA);
    cudaEventRecord(evB, sB);
    cudaStreamWaitEvent(0, evA, 0);
    cudaStreamWaitEvent(0, evB, 0);
    final_kernel<<<1, 256>>>(out);
}

// round 14
// speedup vs baseline: 1.4194x; 1.0087x over previous
#include <cuda_runtime.h>
#include <cuda_fp16.h>
#include <cstdint>

#define NB 16384
#define NV 1024
#define NH 1024
#define NC 64
#define NSTEPS 25
#define NCHAIN (2 * NSTEPS)
#define HALF_B (NB / 2)

// ---------------------------------------------------------------------------
// Scratch (static __device__ allocations; no cudaMalloc anywhere)
// ---------------------------------------------------------------------------
__device__ float g_bmod[NB * NV];               // 64 MB
__device__ float g_cmod[NB * NH];               // 64 MB
__device__ __half g_v[NB * NV];                 // 32 MB (current v, 0/1 fp16)
__device__ __half g_h[NB * NH];                 // 32 MB
__device__ __half g_vd[NB * NV];                // 32 MB (v_data fp16, exact 0/1)
__device__ __half g_Wh[NV * NH];                // W fp16 [V][H]
__device__ __half g_WTh[NH * NV];               // W^T fp16 [H][V]
__device__ float g_fe_d[NB];
__device__ float g_fe_m[NB];
__device__ float g_fep_d[NB * 16];
__device__ float g_fep_m[NB * 16];

// ---------------------------------------------------------------------------
// threefry2x32 (exact JAX semantics, jax_threefry_partitionable)
// ---------------------------------------------------------------------------
__host__ __device__ __forceinline__ void threefry(uint32_t k0, uint32_t k1,
                                                  uint32_t x0, uint32_t x1,
                                                  uint32_t& o0, uint32_t& o1)
{
    uint32_t ks2 = k0 ^ k1 ^ 0x1BD11BDAu;
#define TF_ROT(x, r) (((x) << (r)) | ((x) >> (32 - (r))))
#define TF_RND(r) { x0 += x1; x1 = TF_ROT(x1, r); x1 ^= x0; }
    x0 += k0; x1 += k1;
    TF_RND(13) TF_RND(15) TF_RND(26) TF_RND(6)
    x0 += k1; x1 += ks2 + 1u;
    TF_RND(17) TF_RND(29) TF_RND(16) TF_RND(24)
    x0 += ks2; x1 += k0 + 2u;
    TF_RND(13) TF_RND(15) TF_RND(26) TF_RND(6)
    x0 += k0; x1 += k1 + 3u;
    TF_RND(17) TF_RND(29) TF_RND(16) TF_RND(24)
    x0 += k1; x1 += ks2 + 4u;
    TF_RND(13) TF_RND(15) TF_RND(26) TF_RND(6)
    x0 += ks2; x1 += k0 + 5u;
    o0 = x0; o1 = x1;
#undef TF_RND
#undef TF_ROT
}

__device__ __forceinline__ float urand(uint32_t k0, uint32_t k1, uint32_t idx)
{
    uint32_t a, b;
    threefry(k0, k1, 0u, idx, a, b);
    uint32_t bits = a ^ b;
    return __uint_as_float((bits >> 9) | 0x3F800000u) - 1.0f;
}

// ---------------------------------------------------------------------------
// MMA / ldmatrix / cp.async helpers (baseline PTX, legal on plain sm_103)
// ---------------------------------------------------------------------------
__device__ __forceinline__ uint32_t smem_u32(const void* p) {
    uint32_t a;
    asm("{ .reg .u64 t; cvta.to.shared.u64 t, %1; cvt.u32.u64 %0, t; }" : "=r"(a) : "l"(p));
    return a;
}
__device__ __forceinline__ void ldsm4(uint32_t* r, uint32_t addr) {
    asm volatile("ldmatrix.sync.aligned.m8n8.x4.shared.b16 {%0,%1,%2,%3}, [%4];"
                 : "=r"(r[0]), "=r"(r[1]), "=r"(r[2]), "=r"(r[3]) : "r"(addr));
}
__device__ __forceinline__ void mma_f16(float* d, const uint32_t* a, uint32_t b0, uint32_t b1) {
    asm volatile("mma.sync.aligned.m16n8k16.row.col.f32.f16.f16.f32 "
                 "{%0,%1,%2,%3}, {%4,%5,%6,%7}, {%8,%9}, {%0,%1,%2,%3};"
                 : "+f"(d[0]), "+f"(d[1]), "+f"(d[2]), "+f"(d[3])
                 : "r"(a[0]), "r"(a[1]), "r"(a[2]), "r"(a[3]), "r"(b0), "r"(b1));
}
#define CP_ASYNC16(dst, src) \
    asm volatile("cp.async.cg.shared.global [%0], [%1], 16;" :: "r"(dst), "l"(src))
#define CP_COMMIT() asm volatile("cp.async.commit_group;")
#define CP_WAIT1()  asm volatile("cp.async.wait_group 1;")
#define CP_WAIT0()  asm volatile("cp.async.wait_group 0;")

__device__ __forceinline__ uint32_t swz(uint32_t off) {  // SW128 on 128B rows
    return off ^ ((off >> 3) & 0x70);
}

// ---------------------------------------------------------------------------
// W -> fp16 plane, both orientations
// ---------------------------------------------------------------------------
__global__ void split_kernel(const float* __restrict__ W)
{
    __shared__ __half tf[32][33];
    int bx = blockIdx.x * 32;   // h
    int by = blockIdx.y * 32;   // v
    int tx = threadIdx.x, ty = threadIdx.y;  // 32 x 8
    #pragma unroll
    for (int i = 0; i < 32; i += 8) {
        float w = W[(size_t)(by + ty + i) * NH + bx + tx];
        __half hf = __float2half(w);
        g_Wh[(size_t)(by + ty + i) * NH + bx + tx] = hf;
        tf[ty + i][tx] = hf;
    }
    __syncthreads();
    #pragma unroll
    for (int i = 0; i < 32; i += 8)
        g_WTh[(size_t)(bx + ty + i) * NV + by + tx] = tf[tx][ty + i];
}

// ---------------------------------------------------------------------------
// Conditioning MLP -> b_mod, c_mod  (16 rows per block)
// ---------------------------------------------------------------------------
#define PROWS 16
__global__ void params_kernel(const float* __restrict__ cond, const float* __restrict__ b,
                              const float* __restrict__ c, const float* __restrict__ W1,
                              const float* __restrict__ b1, const float* __restrict__ W2,
                              const float* __restrict__ b2)
{
    __shared__ float sc[PROWS][NC];
    __shared__ float st[PROWS][NC];
    int row0 = blockIdx.x * PROWS;
    int tid = threadIdx.x;  // 256

    for (int i = tid; i < PROWS * NC; i += 256)
        sc[i / NC][i % NC] = cond[(size_t)(row0 + i / NC) * NC + (i % NC)];
    __syncthreads();
    for (int i = tid; i < PROWS * NC; i += 256) {
        int r = i / NC, j = i % NC;
        float s = b1[j];
        #pragma unroll 8
        for (int k = 0; k < NC; k++) s += sc[r][k] * W1[k * NC + j];
        st[r][j] = tanhf(s);
    }
    __syncthreads();

    for (int q = tid; q < NV; q += 256) {
        float ga[PROWS], be[PROWS];
        float ig = b2[q], ib = b2[NV + q];
        #pragma unroll
        for (int r = 0; r < PROWS; r++) { ga[r] = ig; be[r] = ib; }
        for (int k = 0; k < NC; k++) {
            float wg = W2[(size_t)k * 4096 + q];
            float wb = W2[(size_t)k * 4096 + NV + q];
            #pragma unroll
            for (int r = 0; r < PROWS; r++) { ga[r] += st[r][k] * wg; be[r] += st[r][k] * wb; }
        }
        float bq = b[q];
        #pragma unroll
        for (int r = 0; r < PROWS; r++)
            g_bmod[(size_t)(row0 + r) * NV + q] = (1.0f + ga[r]) * bq + be[r];
    }
    for (int q = tid; q < NH; q += 256) {
        float ga[PROWS], be[PROWS];
        float ig = b2[2 * NV + q], ib = b2[2 * NV + NH + q];
        #pragma unroll
        for (int r = 0; r < PROWS; r++) { ga[r] = ig; be[r] = ib; }
        for (int k = 0; k < NC; k++) {
            float wg = W2[(size_t)k * 4096 + 2 * NV + q];
            float wb = W2[(size_t)k * 4096 + 2 * NV + NH + q];
            #pragma unroll
            for (int r = 0; r < PROWS; r++) { ga[r] += st[r][k] * wg; be[r] += st[r][k] * wb; }
        }
        float cq = c[q];
        #pragma unroll
        for (int r = 0; r < PROWS; r++)
            g_cmod[(size_t)(row0 + r) * NH + q] = (1.0f + ga[r]) * cq + be[r];
    }
}

// ---------------------------------------------------------------------------
// init / conversion kernels
// ---------------------------------------------------------------------------
__global__ void init_v_kernel(uint32_t k0, uint32_t k1)
{
    uint32_t i = blockIdx.x * blockDim.x + threadIdx.x;
    float u = urand(k0, k1, i);
    ((uint16_t*)g_v)[i] = (u < 0.5f) ? 0x3C00u : 0u;   // fp16 1.0 / 0.0
}
__global__ void conv_vdata_kernel(const float* __restrict__ vd)
{
    uint32_t i = blockIdx.x * blockDim.x + threadIdx.x;
    g_vd[i] = __float2half(vd[i]);   // v_data is 0/1, exact in fp16
}

// ---------------------------------------------------------------------------
// Fused GEMM (fp16 single plane): Z[128x128 tile] = A @ B^T + bias
//   MODE 0: Out(fp16) = bernoulli(sigmoid(Z)); RNG index = gbase + local idx
//   MODE 1: fe_part[row*16 + bx*2 + half] = sum_{64 cols} softplus(Z)
// 2-stage cp.async, K-chunk 64, warps 2(M)x4(N), z-spill + coalesced epilogue.
// ---------------------------------------------------------------------------
#define CH_STAGE 32768
#define ZSPILL_BYTES (128 * 132 * 4)   // 67584
#define CH_SMEM ((2 * CH_STAGE > ZSPILL_BYTES) ? 2 * CH_STAGE : ZSPILL_BYTES)  // 67584

__device__ __forceinline__ void ch_stage_load(uint32_t s_stage,
    const uint16_t* A, const uint16_t* B, int m0, int n0, int kk, int tid)
{
    #pragma unroll
    for (int r = 0; r < 8; r++) {
        int i = tid + r * 256;          // 0..2047
        int buf = i >> 10;              // 0:A 1:B
        int row = (i >> 3) & 127;
        int ch  = i & 7;
        const char* src = buf == 0
            ? (const char*)A + (size_t)(m0 + row) * 2048 + kk * 128 + ch * 16
            : (const char*)B + (size_t)(n0 + row) * 2048 + kk * 128 + ch * 16;
        uint32_t off = (uint32_t)(row * 128 + ch * 16);
        CP_ASYNC16(s_stage + buf * 16384 + swz(off), src);
    }
    CP_COMMIT();
}

template <int MODE>
__global__ void __launch_bounds__(256, 2)
gemm_kernel(const uint16_t* __restrict__ A, const uint16_t* __restrict__ B,
            const float* __restrict__ bias, uint16_t* __restrict__ Out,
            float* __restrict__ fe_part, uint32_t gbase, uint32_t k0, uint32_t k1)
{
    extern __shared__ char smem[];
    const uint32_t sbase = smem_u32(smem);
    const int tid = threadIdx.x;
    const int wid = tid >> 5, lane = tid & 31;
    const int warp_m = wid & 1, warp_n = wid >> 1;
    const int la = lane & 15, ha = lane >> 4;
    const int m0 = blockIdx.y * 128;
    const int n0 = blockIdx.x * 128;

    float acc[4][4][4];                  // [mt(16m)][n8][frag]
    #pragma unroll
    for (int i = 0; i < 4; i++)
        #pragma unroll
        for (int j = 0; j < 4; j++)
            #pragma unroll
            for (int q = 0; q < 4; q++) acc[i][j][q] = 0.0f;

    ch_stage_load(sbase, A, B, m0, n0, 0, tid);

    #pragma unroll 1
    for (int kk = 0; kk < 16; kk++) {
        const uint32_t s = sbase + (uint32_t)(kk & 1) * CH_STAGE;
        if (kk + 1 < 16) {
            ch_stage_load(sbase + (uint32_t)((kk + 1) & 1) * CH_STAGE, A, B, m0, n0, kk + 1, tid);
            CP_WAIT1();
        } else {
            CP_WAIT0();
        }
        __syncthreads();

        #pragma unroll
        for (int ks = 0; ks < 4; ks++) {
            uint32_t a[4][4];
            #pragma unroll
            for (int mt = 0; mt < 4; mt++) {
                uint32_t off = (uint32_t)((warp_m * 64 + mt * 16 + la) * 128 + ks * 32 + ha * 16);
                ldsm4(a[mt], s + swz(off));
            }
            uint32_t b[2][4];
            #pragma unroll
            for (int g = 0; g < 2; g++) {
                uint32_t off = (uint32_t)((warp_n * 32 + g * 16 + la) * 128 + ks * 32 + ha * 16);
                ldsm4(b[g], s + 16384u + swz(off));
            }
            #pragma unroll
            for (int mt = 0; mt < 4; mt++)
                #pragma unroll
                for (int n8 = 0; n8 < 4; n8++)
                    mma_f16(acc[mt][n8], a[mt], b[n8 >> 1][n8 & 1], b[n8 >> 1][(n8 & 1) + 2]);
        }
        __syncthreads();
    }

    // Spill Z to smem (stride 132 floats)
    float* zs = (float*)smem;
    #pragma unroll
    for (int mt = 0; mt < 4; mt++)
        #pragma unroll
        for (int n8 = 0; n8 < 4; n8++) {
            int r = warp_m * 64 + mt * 16 + (lane >> 2);
            int cc = warp_n * 32 + n8 * 8 + (lane & 3) * 2;
            zs[r * 132 + cc]           = acc[mt][n8][0];
            zs[r * 132 + cc + 1]       = acc[mt][n8][1];
            zs[(r + 8) * 132 + cc]     = acc[mt][n8][2];
            zs[(r + 8) * 132 + cc + 1] = acc[mt][n8][3];
        }
    __syncthreads();

    // Per-thread epilogue: row = tid>>1 (local), 64-col half = tid&1
    const int rloc = tid >> 1;
    const int c0 = (tid & 1) * 64;
    const int row = m0 + rloc;
    const float* zrow = zs + rloc * 132 + c0;
    const float4* bp = (const float4*)(bias + (size_t)row * 1024 + n0 + c0);

    if (MODE == 0) {
        const uint32_t ibase = gbase + (uint32_t)(row * 1024 + n0 + c0);
        uint4* op = (uint4*)(Out + (size_t)row * 1024 + n0 + c0);
        #pragma unroll 1
        for (int j0 = 0; j0 < 64; j0 += 8) {
            float4 bv0 = bp[j0 / 4], bv1 = bp[j0 / 4 + 1];
            float zb[8] = {bv0.x, bv0.y, bv0.z, bv0.w, bv1.x, bv1.y, bv1.z, bv1.w};
            uint32_t pk[4];
            #pragma unroll
            for (int jj = 0; jj < 8; jj += 2) {
                float z0 = zrow[j0 + jj] + zb[jj];
                float z1 = zrow[j0 + jj + 1] + zb[jj + 1];
                float e0 = __expf(-z0), e1 = __expf(-z1);
                float u0 = urand(k0, k1, ibase + (uint32_t)(j0 + jj));
                float u1 = urand(k0, k1, ibase + (uint32_t)(j0 + jj) + 1u);
                uint32_t s0 = (fmaf(u0, e0, u0) < 1.0f) ? 0x3C00u : 0u;  // fp16 1.0
                uint32_t s1 = (fmaf(u1, e1, u1) < 1.0f) ? 0x3C00u : 0u;
                pk[jj >> 1] = s0 | (s1 << 16);
            }
            op[j0 / 8] = make_uint4(pk[0], pk[1], pk[2], pk[3]);
        }
    } else {
        float sp_acc = 0.0f;
        #pragma unroll 1
        for (int j0 = 0; j0 < 64; j0 += 8) {
            float4 bv0 = bp[j0 / 4], bv1 = bp[j0 / 4 + 1];
            float zb[8] = {bv0.x, bv0.y, bv0.z, bv0.w, bv1.x, bv1.y, bv1.z, bv1.w};
            #pragma unroll
            for (int jj = 0; jj < 8; jj++) {
                float z = zrow[j0 + jj] + zb[jj];
                sp_acc += fmaxf(z, 0.0f) + log1pf(expf(-fabsf(z)));
            }
        }
        fe_part[(size_t)row * 16 + blockIdx.x * 2 + (tid & 1)] = sp_acc;
    }
}

// ---------------------------------------------------------------------------
// fe[row] = -(v . bmod_row) - sum(fe_part[row, :16])   (fp16 v)
// ---------------------------------------------------------------------------
__global__ void rowdot_kernel(const __half* __restrict__ v, const float* __restrict__ bmod,
                              const float* __restrict__ part, float* __restrict__ fe)
{
    int row = blockIdx.x;
    int tid = threadIdx.x;  // 256
    float s = 0.0f;
    for (int q = tid; q < NV; q += 256)
        s += __half2float(v[(size_t)row * NV + q]) * bmod[(size_t)row * NV + q];
    __shared__ float red[8];
    #pragma unroll
    for (int off = 16; off; off >>= 1) s += __shfl_down_sync(0xffffffffu, s, off);
    if ((tid & 31) == 0) red[tid >> 5] = s;
    __syncthreads();
    if (tid == 0) {
        float dsum = 0.0f;
        #pragma unroll
        for (int w = 0; w < 8; w++) dsum += red[w];
        float sp = 0.0f;
        #pragma unroll
        for (int j = 0; j < 16; j++) sp += part[(size_t)row * 16 + j];
        fe[row] = -dsum - sp;
    }
}

__global__ void final_kernel(float* __restrict__ out)
{
    int tid = threadIdx.x;  // 256
    double s = 0.0;
    for (int i = tid; i < NB; i += 256)
        s += (double)g_fe_d[i] - (double)g_fe_m[i];
    __shared__ double red[8];
    #pragma unroll
    for (int off = 16; off; off >>= 1) s += __shfl_down_sync(0xffffffffu, s, off);
    if ((tid & 31) == 0) red[tid >> 5] = s;
    __syncthreads();
    if (tid == 0) {
        double t = 0.0;
        #pragma unroll
        for (int w = 0; w < 8; w++) t += red[w];
        out[0] = (float)(t / (double)NB);
    }
}

// ---------------------------------------------------------------------------
// Host orchestration
// ---------------------------------------------------------------------------
static void host_split_keys(uint32_t& sk0, uint32_t& sk1,
                            uint32_t* ck0, uint32_t* ck1)
{
    uint32_t rk0 = 0u, rk1 = 42u;
    uint32_t c0, c1;
    threefry(rk0, rk1, 0u, 0u, c0, c1);    // k_chain
    threefry(rk0, rk1, 0u, 1u, sk0, sk1);  // k_start
    uint32_t k0 = c0, k1 = c1;
    for (int s = 0; s < NSTEPS; s++) {
        uint32_t nk0, nk1, h0, h1, v0, v1;
        threefry(k0, k1, 0u, 0u, nk0, nk1);
        threefry(k0, k1, 0u, 1u, h0, h1);  // kh
        threefry(k0, k1, 0u, 2u, v0, v1);  // kv
        ck0[2 * s] = h0;     ck1[2 * s] = h1;
        ck0[2 * s + 1] = v0; ck1[2 * s + 1] = v1;
        k0 = nk0; k1 = nk1;
    }
}

extern "C" void kernel_launch(void* const* d_in, const int* in_sizes, int n_in,
                              void* d_out, int out_size)
{
    const float* v_data = (const float*)d_in[0];
    const float* cond   = (const float*)d_in[1];
    const float* W      = (const float*)d_in[2];
    const float* b      = (const float*)d_in[3];
    const float* c      = (const float*)d_in[4];
    const float* W1     = (const float*)d_in[5];
    const float* b1     = (const float*)d_in[6];
    const float* W2     = (const float*)d_in[7];
    const float* b2     = (const float*)d_in[8];
    float* out = (float*)d_out;

    uint32_t sk0, sk1;
    uint32_t ck0[NCHAIN], ck1[NCHAIN];
    host_split_keys(sk0, sk1, ck0, ck1);

    // Streams/events created once on the (uncaptured) correctness call.
    static cudaStream_t sA = nullptr, sB = nullptr;
    static cudaEvent_t ev0 = nullptr, evA = nullptr, evB = nullptr;
    static cudaEvent_t evSA = nullptr, evSB = nullptr;
    if (!sA) {
        cudaStreamCreateWithFlags(&sA, cudaStreamNonBlocking);
        cudaStreamCreateWithFlags(&sB, cudaStreamNonBlocking);
        cudaEventCreateWithFlags(&ev0, cudaEventDisableTiming);
        cudaEventCreateWithFlags(&evA, cudaEventDisableTiming);
        cudaEventCreateWithFlags(&evB, cudaEventDisableTiming);
        cudaEventCreateWithFlags(&evSA, cudaEventDisableTiming);
        cudaEventCreateWithFlags(&evSB, cudaEventDisableTiming);
    }

    cudaFuncSetAttribute(gemm_kernel<0>, cudaFuncAttributeMaxDynamicSharedMemorySize, CH_SMEM);
    cudaFuncSetAttribute(gemm_kernel<1>, cudaFuncAttributeMaxDynamicSharedMemorySize, CH_SMEM);

    uint16_t *p_v, *p_h, *p_vd, *p_Wh, *p_WTh;
    float *p_bmod, *p_cmod, *p_fed, *p_fem, *p_fpd, *p_fpm;
    cudaGetSymbolAddress((void**)&p_v, g_v);
    cudaGetSymbolAddress((void**)&p_h, g_h);
    cudaGetSymbolAddress((void**)&p_vd, g_vd);
    cudaGetSymbolAddress((void**)&p_Wh, g_Wh);
    cudaGetSymbolAddress((void**)&p_WTh, g_WTh);
    cudaGetSymbolAddress((void**)&p_bmod, g_bmod);
    cudaGetSymbolAddress((void**)&p_cmod, g_cmod);
    cudaGetSymbolAddress((void**)&p_fed, g_fe_d);
    cudaGetSymbolAddress((void**)&p_fem, g_fe_m);
    cudaGetSymbolAddress((void**)&p_fpd, g_fep_d);
    cudaGetSymbolAddress((void**)&p_fpm, g_fep_m);

    // Fork FIRST (capture-legal), then distribute setup across branches.
    cudaEventRecord(ev0, 0);
    cudaStreamWaitEvent(sA, ev0, 0);
    cudaStreamWaitEvent(sB, ev0, 0);

    split_kernel<<<dim3(32, 32), dim3(32, 8), 0, sA>>>(W);
    init_v_kernel<<<(NB * NV) / 256, 256, 0, sA>>>(sk0, sk1);
    params_kernel<<<NB / PROWS, 256, 0, sB>>>(cond, b, c, W1, b1, W2, b2);
    conv_vdata_kernel<<<(NB * NV) / 256, 256, 0, 0>>>(v_data);

    // Cross-join setup: chain A needs params (sB); chain B needs split/init_v
    // (sA); default FE-data needs both + conv_vdata (already ordered on 0).
    cudaEventRecord(evSA, sA);
    cudaEventRecord(evSB, sB);
    cudaStreamWaitEvent(sA, evSB, 0);
    cudaStreamWaitEvent(sB, evSA, 0);
    cudaStreamWaitEvent(0, evSA, 0);
    cudaStreamWaitEvent(0, evSB, 0);

    // FE-data (independent of the chain) on default stream — fills chain-era gaps.
    {
        dim3 fgrid(8, NB / 128);
        gemm_kernel<1><<<fgrid, 256, CH_SMEM, 0>>>(
            p_vd, p_WTh, p_cmod, nullptr, p_fpd, 0u, 0u, 0u);
        rowdot_kernel<<<NB, 256, 0, 0>>>((const __half*)p_vd, p_bmod, p_fpd, p_fed);
    }

    const dim3 hgrid(8, HALF_B / 128);   // (8, 64)
    const uint32_t roff[2] = { 0u, (uint32_t)HALF_B };
    cudaStream_t streams[2] = { sA, sB };

    for (int half = 0; half < 2; half++) {
        const size_t eo = (size_t)roff[half] * 1024;    // element offset
        const uint32_t gb = roff[half] * 1024u;         // global RNG index base
        cudaStream_t st = streams[half];
        for (int s = 0; s < NCHAIN; s++) {
            const int even = !(s & 1);
            gemm_kernel<0><<<hgrid, 256, CH_SMEM, st>>>(
                (even ? p_v : p_h) + eo,
                even ? p_WTh : p_Wh,
                (even ? p_cmod : p_bmod) + eo,
                (even ? p_h : p_v) + eo,
                nullptr, gb, ck0[s], ck1[s]);
        }
        // Free energy (model term) for this half
        gemm_kernel<1><<<hgrid, 256, CH_SMEM, st>>>(
            p_v + eo, p_WTh, p_cmod + eo, nullptr, p_fpm + (size_t)roff[half] * 16, 0u, 0u, 0u);
        rowdot_kernel<<<HALF_B, 256, 0, st>>>(
            (const __half*)(p_v + eo), p_bmod + eo, p_fpm + (size_t)roff[half] * 16, p_fem + roff[half]);
    }

    // Join and reduce (FE-data already ordered on default stream)
    cudaEventRecord(evA, sA);
    cudaEventRecord(evB, sB);
    cudaStreamWaitEvent(0, evA, 0);
    cudaStreamWaitEvent(0, evB, 0);
    final_kernel<<<1, 256>>>(out);
}

// round 15
// speedup vs baseline: 1.4445x; 1.0176x over previous
#include <cuda_runtime.h>
#include <cuda_fp16.h>
#include <cstdint>

#define NB 16384
#define NV 1024
#define NH 1024
#define NC 64
#define NSTEPS 25
#define NCHAIN (2 * NSTEPS)
#define HALF_B (NB / 2)

// ---------------------------------------------------------------------------
// Scratch (static __device__ allocations; no cudaMalloc anywhere)
// ---------------------------------------------------------------------------
__device__ float g_bmod[NB * NV];               // 64 MB
__device__ float g_cmod[NB * NH];               // 64 MB
__device__ __half g_v[NB * NV];                 // 32 MB (current v, 0/1 fp16)
__device__ __half g_h[NB * NH];                 // 32 MB
__device__ __half g_vd[NB * NV];                // 32 MB (v_data fp16, exact 0/1)
__device__ __half g_Wh[NV * NH];                // W fp16 [V][H]
__device__ __half g_WTh[NH * NV];               // W^T fp16 [H][V]
__device__ float g_fe_d[NB];
__device__ float g_fe_m[NB];
__device__ float g_fep_d[NB * 16];
__device__ float g_fep_m[NB * 16];

// ---------------------------------------------------------------------------
// threefry2x32 (exact JAX semantics, jax_threefry_partitionable)
// ---------------------------------------------------------------------------
__host__ __device__ __forceinline__ void threefry(uint32_t k0, uint32_t k1,
                                                  uint32_t x0, uint32_t x1,
                                                  uint32_t& o0, uint32_t& o1)
{
    uint32_t ks2 = k0 ^ k1 ^ 0x1BD11BDAu;
#define TF_ROT(x, r) (((x) << (r)) | ((x) >> (32 - (r))))
#define TF_RND(r) { x0 += x1; x1 = TF_ROT(x1, r); x1 ^= x0; }
    x0 += k0; x1 += k1;
    TF_RND(13) TF_RND(15) TF_RND(26) TF_RND(6)
    x0 += k1; x1 += ks2 + 1u;
    TF_RND(17) TF_RND(29) TF_RND(16) TF_RND(24)
    x0 += ks2; x1 += k0 + 2u;
    TF_RND(13) TF_RND(15) TF_RND(26) TF_RND(6)
    x0 += k0; x1 += k1 + 3u;
    TF_RND(17) TF_RND(29) TF_RND(16) TF_RND(24)
    x0 += k1; x1 += ks2 + 4u;
    TF_RND(13) TF_RND(15) TF_RND(26) TF_RND(6)
    x0 += ks2; x1 += k0 + 5u;
    o0 = x0; o1 = x1;
#undef TF_RND
#undef TF_ROT
}

__device__ __forceinline__ float urand(uint32_t k0, uint32_t k1, uint32_t idx)
{
    uint32_t a, b;
    threefry(k0, k1, 0u, idx, a, b);
    uint32_t bits = a ^ b;
    return __uint_as_float((bits >> 9) | 0x3F800000u) - 1.0f;
}

// ---------------------------------------------------------------------------
// MMA / ldmatrix / cp.async helpers (baseline PTX, legal on plain sm_103)
// ---------------------------------------------------------------------------
__device__ __forceinline__ uint32_t smem_u32(const void* p) {
    uint32_t a;
    asm("{ .reg .u64 t; cvta.to.shared.u64 t, %1; cvt.u32.u64 %0, t; }" : "=r"(a) : "l"(p));
    return a;
}
__device__ __forceinline__ void ldsm4(uint32_t* r, uint32_t addr) {
    asm volatile("ldmatrix.sync.aligned.m8n8.x4.shared.b16 {%0,%1,%2,%3}, [%4];"
                 : "=r"(r[0]), "=r"(r[1]), "=r"(r[2]), "=r"(r[3]) : "r"(addr));
}
__device__ __forceinline__ void mma_f16(float* d, const uint32_t* a, uint32_t b0, uint32_t b1) {
    asm volatile("mma.sync.aligned.m16n8k16.row.col.f32.f16.f16.f32 "
                 "{%0,%1,%2,%3}, {%4,%5,%6,%7}, {%8,%9}, {%0,%1,%2,%3};"
                 : "+f"(d[0]), "+f"(d[1]), "+f"(d[2]), "+f"(d[3])
                 : "r"(a[0]), "r"(a[1]), "r"(a[2]), "r"(a[3]), "r"(b0), "r"(b1));
}
#define CP_ASYNC16(dst, src) \
    asm volatile("cp.async.cg.shared.global [%0], [%1], 16;" :: "r"(dst), "l"(src))
#define CP_COMMIT() asm volatile("cp.async.commit_group;")
#define CP_WAIT1()  asm volatile("cp.async.wait_group 1;")
#define CP_WAIT0()  asm volatile("cp.async.wait_group 0;")

__device__ __forceinline__ uint32_t swz(uint32_t off) {  // SW128 on 128B rows
    return off ^ ((off >> 3) & 0x70);
}

// ---------------------------------------------------------------------------
// W -> fp16 plane, both orientations
// ---------------------------------------------------------------------------
__global__ void split_kernel(const float* __restrict__ W)
{
    __shared__ __half tf[32][33];
    int bx = blockIdx.x * 32;   // h
    int by = blockIdx.y * 32;   // v
    int tx = threadIdx.x, ty = threadIdx.y;  // 32 x 8
    #pragma unroll
    for (int i = 0; i < 32; i += 8) {
        float w = W[(size_t)(by + ty + i) * NH + bx + tx];
        __half hf = __float2half(w);
        g_Wh[(size_t)(by + ty + i) * NH + bx + tx] = hf;
        tf[ty + i][tx] = hf;
    }
    __syncthreads();
    #pragma unroll
    for (int i = 0; i < 32; i += 8)
        g_WTh[(size_t)(bx + ty + i) * NV + by + tx] = tf[tx][ty + i];
}

// ---------------------------------------------------------------------------
// Conditioning MLP, split into independent halves:
//   params_c_kernel -> c_mod (needed by chain step 0)
//   params_b_kernel -> b_mod (needed from chain step 1 and rowdot)
// Both recompute the tiny tanh hidden layer (16 rows per block).
// ---------------------------------------------------------------------------
#define PROWS 16

__device__ __forceinline__ void params_hidden(const float* __restrict__ cond,
                                              const float* __restrict__ W1,
                                              const float* __restrict__ b1,
                                              int row0, int tid,
                                              float sc[PROWS][NC], float st[PROWS][NC])
{
    for (int i = tid; i < PROWS * NC; i += 256)
        sc[i / NC][i % NC] = cond[(size_t)(row0 + i / NC) * NC + (i % NC)];
    __syncthreads();
    for (int i = tid; i < PROWS * NC; i += 256) {
        int r = i / NC, j = i % NC;
        float s = b1[j];
        #pragma unroll 8
        for (int k = 0; k < NC; k++) s += sc[r][k] * W1[k * NC + j];
        st[r][j] = tanhf(s);
    }
    __syncthreads();
}

__global__ void params_c_kernel(const float* __restrict__ cond, const float* __restrict__ c,
                                const float* __restrict__ W1, const float* __restrict__ b1,
                                const float* __restrict__ W2, const float* __restrict__ b2)
{
    __shared__ float sc[PROWS][NC];
    __shared__ float st[PROWS][NC];
    int row0 = blockIdx.x * PROWS;
    int tid = threadIdx.x;  // 256
    params_hidden(cond, W1, b1, row0, tid, sc, st);

    for (int q = tid; q < NH; q += 256) {
        float ga[PROWS], be[PROWS];
        float ig = b2[2 * NV + q], ib = b2[2 * NV + NH + q];
        #pragma unroll
        for (int r = 0; r < PROWS; r++) { ga[r] = ig; be[r] = ib; }
        for (int k = 0; k < NC; k++) {
            float wg = W2[(size_t)k * 4096 + 2 * NV + q];
            float wb = W2[(size_t)k * 4096 + 2 * NV + NH + q];
            #pragma unroll
            for (int r = 0; r < PROWS; r++) { ga[r] += st[r][k] * wg; be[r] += st[r][k] * wb; }
        }
        float cq = c[q];
        #pragma unroll
        for (int r = 0; r < PROWS; r++)
            g_cmod[(size_t)(row0 + r) * NH + q] = (1.0f + ga[r]) * cq + be[r];
    }
}

__global__ void params_b_kernel(const float* __restrict__ cond, const float* __restrict__ b,
                                const float* __restrict__ W1, const float* __restrict__ b1,
                                const float* __restrict__ W2, const float* __restrict__ b2)
{
    __shared__ float sc[PROWS][NC];
    __shared__ float st[PROWS][NC];
    int row0 = blockIdx.x * PROWS;
    int tid = threadIdx.x;  // 256
    params_hidden(cond, W1, b1, row0, tid, sc, st);

    for (int q = tid; q < NV; q += 256) {
        float ga[PROWS], be[PROWS];
        float ig = b2[q], ib = b2[NV + q];
        #pragma unroll
        for (int r = 0; r < PROWS; r++) { ga[r] = ig; be[r] = ib; }
        for (int k = 0; k < NC; k++) {
            float wg = W2[(size_t)k * 4096 + q];
            float wb = W2[(size_t)k * 4096 + NV + q];
            #pragma unroll
            for (int r = 0; r < PROWS; r++) { ga[r] += st[r][k] * wg; be[r] += st[r][k] * wb; }
        }
        float bq = b[q];
        #pragma unroll
        for (int r = 0; r < PROWS; r++)
            g_bmod[(size_t)(row0 + r) * NV + q] = (1.0f + ga[r]) * bq + be[r];
    }
}

// ---------------------------------------------------------------------------
// init / conversion kernels
// ---------------------------------------------------------------------------
__global__ void init_v_kernel(uint32_t k0, uint32_t k1)
{
    uint32_t i = blockIdx.x * blockDim.x + threadIdx.x;
    float u = urand(k0, k1, i);
    ((uint16_t*)g_v)[i] = (u < 0.5f) ? 0x3C00u : 0u;   // fp16 1.0 / 0.0
}
__global__ void conv_vdata_kernel(const float* __restrict__ vd)
{
    uint32_t i = blockIdx.x * blockDim.x + threadIdx.x;
    g_vd[i] = __float2half(vd[i]);   // v_data is 0/1, exact in fp16
}

// ---------------------------------------------------------------------------
// Fused GEMM (fp16 single plane): Z[128x128 tile] = A @ B^T + bias
//   MODE 0: Out(fp16) = bernoulli(sigmoid(Z)); RNG index = gbase + local idx
//   MODE 1: fe_part[row*16 + bx*2 + half] = sum_{64 cols} softplus(Z)
// 2-stage cp.async, K-chunk 64, warps 2(M)x4(N), z-spill + coalesced epilogue.
// ---------------------------------------------------------------------------
#define CH_STAGE 32768
#define ZSPILL_BYTES (128 * 132 * 4)   // 67584
#define CH_SMEM ((2 * CH_STAGE > ZSPILL_BYTES) ? 2 * CH_STAGE : ZSPILL_BYTES)  // 67584

__device__ __forceinline__ void ch_stage_load(uint32_t s_stage,
    const uint16_t* A, const uint16_t* B, int m0, int n0, int kk, int tid)
{
    #pragma unroll
    for (int r = 0; r < 8; r++) {
        int i = tid + r * 256;          // 0..2047
        int buf = i >> 10;              // 0:A 1:B
        int row = (i >> 3) & 127;
        int ch  = i & 7;
        const char* src = buf == 0
            ? (const char*)A + (size_t)(m0 + row) * 2048 + kk * 128 + ch * 16
            : (const char*)B + (size_t)(n0 + row) * 2048 + kk * 128 + ch * 16;
        uint32_t off = (uint32_t)(row * 128 + ch * 16);
        CP_ASYNC16(s_stage + buf * 16384 + swz(off), src);
    }
    CP_COMMIT();
}

template <int MODE>
__global__ void __launch_bounds__(256, 2)
gemm_kernel(const uint16_t* __restrict__ A, const uint16_t* __restrict__ B,
            const float* __restrict__ bias, uint16_t* __restrict__ Out,
            float* __restrict__ fe_part, uint32_t gbase, uint32_t k0, uint32_t k1)
{
    extern __shared__ char smem[];
    const uint32_t sbase = smem_u32(smem);
    const int tid = threadIdx.x;
    const int wid = tid >> 5, lane = tid & 31;
    const int warp_m = wid & 1, warp_n = wid >> 1;
    const int la = lane & 15, ha = lane >> 4;
    const int m0 = blockIdx.y * 128;
    const int n0 = blockIdx.x * 128;

    float acc[4][4][4];                  // [mt(16m)][n8][frag]
    #pragma unroll
    for (int i = 0; i < 4; i++)
        #pragma unroll
        for (int j = 0; j < 4; j++)
            #pragma unroll
            for (int q = 0; q < 4; q++) acc[i][j][q] = 0.0f;

    ch_stage_load(sbase, A, B, m0, n0, 0, tid);

    #pragma unroll 1
    for (int kk = 0; kk < 16; kk++) {
        const uint32_t s = sbase + (uint32_t)(kk & 1) * CH_STAGE;
        if (kk + 1 < 16) {
            ch_stage_load(sbase + (uint32_t)((kk + 1) & 1) * CH_STAGE, A, B, m0, n0, kk + 1, tid);
            CP_WAIT1();
        } else {
            CP_WAIT0();
        }
        __syncthreads();

        #pragma unroll
        for (int ks = 0; ks < 4; ks++) {
            uint32_t a[4][4];
            #pragma unroll
            for (int mt = 0; mt < 4; mt++) {
                uint32_t off = (uint32_t)((warp_m * 64 + mt * 16 + la) * 128 + ks * 32 + ha * 16);
                ldsm4(a[mt], s + swz(off));
            }
            uint32_t b[2][4];
            #pragma unroll
            for (int g = 0; g < 2; g++) {
                uint32_t off = (uint32_t)((warp_n * 32 + g * 16 + la) * 128 + ks * 32 + ha * 16);
                ldsm4(b[g], s + 16384u + swz(off));
            }
            #pragma unroll
            for (int mt = 0; mt < 4; mt++)
                #pragma unroll
                for (int n8 = 0; n8 < 4; n8++)
                    mma_f16(acc[mt][n8], a[mt], b[n8 >> 1][n8 & 1], b[n8 >> 1][(n8 & 1) + 2]);
        }
        __syncthreads();
    }

    // Spill Z to smem (stride 132 floats)
    float* zs = (float*)smem;
    #pragma unroll
    for (int mt = 0; mt < 4; mt++)
        #pragma unroll
        for (int n8 = 0; n8 < 4; n8++) {
            int r = warp_m * 64 + mt * 16 + (lane >> 2);
            int cc = warp_n * 32 + n8 * 8 + (lane & 3) * 2;
            zs[r * 132 + cc]           = acc[mt][n8][0];
            zs[r * 132 + cc + 1]       = acc[mt][n8][1];
            zs[(r + 8) * 132 + cc]     = acc[mt][n8][2];
            zs[(r + 8) * 132 + cc + 1] = acc[mt][n8][3];
        }
    __syncthreads();

    // Per-thread epilogue: row = tid>>1 (local), 64-col half = tid&1
    const int rloc = tid >> 1;
    const int c0 = (tid & 1) * 64;
    const int row = m0 + rloc;
    const float* zrow = zs + rloc * 132 + c0;
    const float4* bp = (const float4*)(bias + (size_t)row * 1024 + n0 + c0);

    if (MODE == 0) {
        const uint32_t ibase = gbase + (uint32_t)(row * 1024 + n0 + c0);
        uint4* op = (uint4*)(Out + (size_t)row * 1024 + n0 + c0);
        #pragma unroll 1
        for (int j0 = 0; j0 < 64; j0 += 8) {
            float4 bv0 = bp[j0 / 4], bv1 = bp[j0 / 4 + 1];
            float zb[8] = {bv0.x, bv0.y, bv0.z, bv0.w, bv1.x, bv1.y, bv1.z, bv1.w};
            uint32_t pk[4];
            #pragma unroll
            for (int jj = 0; jj < 8; jj += 2) {
                float z0 = zrow[j0 + jj] + zb[jj];
                float z1 = zrow[j0 + jj + 1] + zb[jj + 1];
                float e0 = __expf(-z0), e1 = __expf(-z1);
                float u0 = urand(k0, k1, ibase + (uint32_t)(j0 + jj));
                float u1 = urand(k0, k1, ibase + (uint32_t)(j0 + jj) + 1u);
                uint32_t s0 = (fmaf(u0, e0, u0) < 1.0f) ? 0x3C00u : 0u;  // fp16 1.0
                uint32_t s1 = (fmaf(u1, e1, u1) < 1.0f) ? 0x3C00u : 0u;
                pk[jj >> 1] = s0 | (s1 << 16);
            }
            op[j0 / 8] = make_uint4(pk[0], pk[1], pk[2], pk[3]);
        }
    } else {
        float sp_acc = 0.0f;
        #pragma unroll 1
        for (int j0 = 0; j0 < 64; j0 += 8) {
            float4 bv0 = bp[j0 / 4], bv1 = bp[j0 / 4 + 1];
            float zb[8] = {bv0.x, bv0.y, bv0.z, bv0.w, bv1.x, bv1.y, bv1.z, bv1.w};
            #pragma unroll
            for (int jj = 0; jj < 8; jj++) {
                float z = zrow[j0 + jj] + zb[jj];
                sp_acc += fmaxf(z, 0.0f) + log1pf(expf(-fabsf(z)));
            }
        }
        fe_part[(size_t)row * 16 + blockIdx.x * 2 + (tid & 1)] = sp_acc;
    }
}

// ---------------------------------------------------------------------------
// fe[row] = -(v . bmod_row) - sum(fe_part[row, :16])   (fp16 v)
// ---------------------------------------------------------------------------
__global__ void rowdot_kernel(const __half* __restrict__ v, const float* __restrict__ bmod,
                              const float* __restrict__ part, float* __restrict__ fe)
{
    int row = blockIdx.x;
    int tid = threadIdx.x;  // 256
    float s = 0.0f;
    for (int q = tid; q < NV; q += 256)
        s += __half2float(v[(size_t)row * NV + q]) * bmod[(size_t)row * NV + q];
    __shared__ float red[8];
    #pragma unroll
    for (int off = 16; off; off >>= 1) s += __shfl_down_sync(0xffffffffu, s, off);
    if ((tid & 31) == 0) red[tid >> 5] = s;
    __syncthreads();
    if (tid == 0) {
        float dsum = 0.0f;
        #pragma unroll
        for (int w = 0; w < 8; w++) dsum += red[w];
        float sp = 0.0f;
        #pragma unroll
        for (int j = 0; j < 16; j++) sp += part[(size_t)row * 16 + j];
        fe[row] = -dsum - sp;
    }
}

__global__ void final_kernel(float* __restrict__ out)
{
    int tid = threadIdx.x;  // 256
    double s = 0.0;
    for (int i = tid; i < NB; i += 256)
        s += (double)g_fe_d[i] - (double)g_fe_m[i];
    __shared__ double red[8];
    #pragma unroll
    for (int off = 16; off; off >>= 1) s += __shfl_down_sync(0xffffffffu, s, off);
    if ((tid & 31) == 0) red[tid >> 5] = s;
    __syncthreads();
    if (tid == 0) {
        double t = 0.0;
        #pragma unroll
        for (int w = 0; w < 8; w++) t += red[w];
        out[0] = (float)(t / (double)NB);
    }
}

// ---------------------------------------------------------------------------
// Host orchestration
// ---------------------------------------------------------------------------
static void host_split_keys(uint32_t& sk0, uint32_t& sk1,
                            uint32_t* ck0, uint32_t* ck1)
{
    uint32_t rk0 = 0u, rk1 = 42u;
    uint32_t c0, c1;
    threefry(rk0, rk1, 0u, 0u, c0, c1);    // k_chain
    threefry(rk0, rk1, 0u, 1u, sk0, sk1);  // k_start
    uint32_t k0 = c0, k1 = c1;
    for (int s = 0; s < NSTEPS; s++) {
        uint32_t nk0, nk1, h0, h1, v0, v1;
        threefry(k0, k1, 0u, 0u, nk0, nk1);
        threefry(k0, k1, 0u, 1u, h0, h1);  // kh
        threefry(k0, k1, 0u, 2u, v0, v1);  // kv
        ck0[2 * s] = h0;     ck1[2 * s] = h1;
        ck0[2 * s + 1] = v0; ck1[2 * s + 1] = v1;
        k0 = nk0; k1 = nk1;
    }
}

extern "C" void kernel_launch(void* const* d_in, const int* in_sizes, int n_in,
                              void* d_out, int out_size)
{
    const float* v_data = (const float*)d_in[0];
    const float* cond   = (const float*)d_in[1];
    const float* W      = (const float*)d_in[2];
    const float* b      = (const float*)d_in[3];
    const float* c      = (const float*)d_in[4];
    const float* W1     = (const float*)d_in[5];
    const float* b1     = (const float*)d_in[6];
    const float* W2     = (const float*)d_in[7];
    const float* b2     = (const float*)d_in[8];
    float* out = (float*)d_out;

    uint32_t sk0, sk1;
    uint32_t ck0[NCHAIN], ck1[NCHAIN];
    host_split_keys(sk0, sk1, ck0, ck1);

    // Streams/events created once on the (uncaptured) correctness call.
    static cudaStream_t sA = nullptr, sB = nullptr;
    static cudaEvent_t ev0 = nullptr, evA = nullptr, evB = nullptr;
    static cudaEvent_t evSA = nullptr, evSC = nullptr, evBM = nullptr;
    if (!sA) {
        cudaStreamCreateWithFlags(&sA, cudaStreamNonBlocking);
        cudaStreamCreateWithFlags(&sB, cudaStreamNonBlocking);
        cudaEventCreateWithFlags(&ev0, cudaEventDisableTiming);
        cudaEventCreateWithFlags(&evA, cudaEventDisableTiming);
        cudaEventCreateWithFlags(&evB, cudaEventDisableTiming);
        cudaEventCreateWithFlags(&evSA, cudaEventDisableTiming);
        cudaEventCreateWithFlags(&evSC, cudaEventDisableTiming);
        cudaEventCreateWithFlags(&evBM, cudaEventDisableTiming);
    }

    cudaFuncSetAttribute(gemm_kernel<0>, cudaFuncAttributeMaxDynamicSharedMemorySize, CH_SMEM);
    cudaFuncSetAttribute(gemm_kernel<1>, cudaFuncAttributeMaxDynamicSharedMemorySize, CH_SMEM);

    uint16_t *p_v, *p_h, *p_vd, *p_Wh, *p_WTh;
    float *p_bmod, *p_cmod, *p_fed, *p_fem, *p_fpd, *p_fpm;
    cudaGetSymbolAddress((void**)&p_v, g_v);
    cudaGetSymbolAddress((void**)&p_h, g_h);
    cudaGetSymbolAddress((void**)&p_vd, g_vd);
    cudaGetSymbolAddress((void**)&p_Wh, g_Wh);
    cudaGetSymbolAddress((void**)&p_WTh, g_WTh);
    cudaGetSymbolAddress((void**)&p_bmod, g_bmod);
    cudaGetSymbolAddress((void**)&p_cmod, g_cmod);
    cudaGetSymbolAddress((void**)&p_fed, g_fe_d);
    cudaGetSymbolAddress((void**)&p_fem, g_fe_m);
    cudaGetSymbolAddress((void**)&p_fpd, g_fep_d);
    cudaGetSymbolAddress((void**)&p_fpm, g_fep_m);

    // Fork FIRST (capture-legal), then distribute setup across branches.
    cudaEventRecord(ev0, 0);
    cudaStreamWaitEvent(sA, ev0, 0);
    cudaStreamWaitEvent(sB, ev0, 0);

    // sA: W planes + v_start; sB: c_mod (needed by step 0);
    // default: b_mod (needed from step 1) + v_data conversion.
    split_kernel<<<dim3(32, 32), dim3(32, 8), 0, sA>>>(W);
    init_v_kernel<<<(NB * NV) / 256, 256, 0, sA>>>(sk0, sk1);
    params_c_kernel<<<NB / PROWS, 256, 0, sB>>>(cond, c, W1, b1, W2, b2);
    params_b_kernel<<<NB / PROWS, 256, 0, 0>>>(cond, b, W1, b1, W2, b2);
    conv_vdata_kernel<<<(NB * NV) / 256, 256, 0, 0>>>(v_data);

    // Join: step 0 needs (split, init_v) + c_mod.
    cudaEventRecord(evSA, sA);
    cudaEventRecord(evSC, sB);
    cudaEventRecord(evBM, 0);            // b_mod + v_data ready
    cudaStreamWaitEvent(sA, evSC, 0);
    cudaStreamWaitEvent(sB, evSA, 0);
    cudaStreamWaitEvent(0, evSA, 0);
    cudaStreamWaitEvent(0, evSC, 0);

    // FE-data (independent of the chain) on default stream — fills chain-era gaps.
    {
        dim3 fgrid(8, NB / 128);
        gemm_kernel<1><<<fgrid, 256, CH_SMEM, 0>>>(
            p_vd, p_WTh, p_cmod, nullptr, p_fpd, 0u, 0u, 0u);
        rowdot_kernel<<<NB, 256, 0, 0>>>((const __half*)p_vd, p_bmod, p_fpd, p_fed);
    }

    const dim3 hgrid(8, HALF_B / 128);   // (8, 64)
    const uint32_t roff[2] = { 0u, (uint32_t)HALF_B };
    cudaStream_t streams[2] = { sA, sB };

    for (int half = 0; half < 2; half++) {
        const size_t eo = (size_t)roff[half] * 1024;    // element offset
        const uint32_t gb = roff[half] * 1024u;         // global RNG index base
        cudaStream_t st = streams[half];
        for (int s = 0; s < NCHAIN; s++) {
            if (s == 1) cudaStreamWaitEvent(st, evBM, 0);   // b_mod ready before v-step
            const int even = !(s & 1);
            gemm_kernel<0><<<hgrid, 256, CH_SMEM, st>>>(
                (even ? p_v : p_h) + eo,
                even ? p_WTh : p_Wh,
                (even ? p_cmod : p_bmod) + eo,
                (even ? p_h : p_v) + eo,
                nullptr, gb, ck0[s], ck1[s]);
        }
        // Free energy (model term) for this half
        gemm_kernel<1><<<hgrid, 256, CH_SMEM, st>>>(
            p_v + eo, p_WTh, p_cmod + eo, nullptr, p_fpm + (size_t)roff[half] * 16, 0u, 0u, 0u);
        rowdot_kernel<<<HALF_B, 256, 0, st>>>(
            (const __half*)(p_v + eo), p_bmod + eo, p_fpm + (size_t)roff[half] * 16, p_fem + roff[half]);
    }

    // Join and reduce (FE-data already ordered on default stream)
    cudaEventRecord(evA, sA);
    cudaEventRecord(evB, sB);
    cudaStreamWaitEvent(0, evA, 0);
    cudaStreamWaitEvent(0, evB, 0);
    final_kernel<<<1, 256>>>(out);
}